// round 1
// baseline (speedup 1.0000x reference)
#include <cuda_runtime.h>
#include <cuda_bf16.h>
#include <math.h>

#define NP   512
#define MNP  4096
#define BSZ  8
#define DIM  256
#define NH   8
#define TOPK 32
#define FF   2048
#define HD   32
#define LN_EPS 1e-5f
#define ATT_SCALE 0.17677669529663687f   /* 1/sqrt(32) */

// ---------------------------------------------------------------------------
// Scratch (device globals: allocation-free per harness rules)
// ---------------------------------------------------------------------------
__device__ float g_sim   [BSZ * NP * MNP];     // 67 MB
__device__ float g_mnorm [MNP * BSZ];          // inv norms, flat (m*BSZ+b)
__device__ int   g_rns   [BSZ * NP * TOPK];
__device__ float g_K     [MNP * BSZ * DIM];
__device__ float g_V     [MNP * BSZ * DIM];
__device__ float g_Q     [NP * BSZ * DIM];
__device__ float g_cross [NP * BSZ * DIM];
__device__ float g_t1    [NP * BSZ * DIM];
__device__ float g_Q2    [NP * BSZ * DIM];
__device__ float g_K2    [NP * BSZ * DIM];
__device__ float g_V2    [NP * BSZ * DIM];
__device__ float g_sc2   [BSZ * NH * NP * NP]; // 67 MB
__device__ float g_sa    [NP * BSZ * DIM];
__device__ float g_sa2   [NP * BSZ * DIM];
__device__ float g_t2    [NP * BSZ * DIM];
__device__ float g_ffh   [NP * BSZ * FF];      // 33 MB
__device__ float g_ffo   [NP * BSZ * DIM];

// ---------------------------------------------------------------------------
// Generic batched SGEMM:  C = act( alpha * (A (+A2)) @ op(B) + bias )
//   A: (R,K) row-major, leading dim lda, batch offset z1*sA1+z2*sA2
//   TRANS_B=true : B[c,k]  (weight layout, NT)   ldb = stride between c rows
//   TRANS_B=false: B[k,c]  (NN)                  ldb = stride between k rows
//   ACT: 0=none, 1=exact GELU
// Tiles: 64x64x16, 256 threads, 4x4 per thread.
// ---------------------------------------------------------------------------
template<bool TRANS_B, int ACT>
__global__ void sgemm_kernel(
    const float* __restrict__ A, const float* __restrict__ A2,
    const float* __restrict__ B, const float* __restrict__ bias,
    float* __restrict__ C,
    int R, int Cc, int K,
    int lda, int ldb, int ldc,
    long sA1, long sA2, long sB1, long sB2, long sC1, long sC2,
    int Z2, float alpha)
{
    __shared__ float As[16][64];
    __shared__ float Bs[16][64];

    const int z  = blockIdx.z;
    const int z1 = z / Z2, z2 = z % Z2;
    A += z1 * sA1 + z2 * sA2;
    if (A2) A2 += z1 * sA1 + z2 * sA2;
    B += z1 * sB1 + z2 * sB2;
    C += z1 * sC1 + z2 * sC2;

    const int row0 = blockIdx.y * 64;
    const int col0 = blockIdx.x * 64;
    const int t  = threadIdx.x;
    const int tx = t & 15, ty = t >> 4;

    const int ar = t >> 2;          // 0..63
    const int ak = (t & 3) << 2;    // 0,4,8,12

    float acc[4][4] = {};

    for (int k0 = 0; k0 < K; k0 += 16) {
        // --- stage A tile (transposed into As[k][m]) ---
        {
            int r = row0 + ar;
            float4 v = make_float4(0.f, 0.f, 0.f, 0.f);
            if (r < R) {
                v = *reinterpret_cast<const float4*>(&A[(long)r * lda + k0 + ak]);
                if (A2) {
                    float4 w = *reinterpret_cast<const float4*>(&A2[(long)r * lda + k0 + ak]);
                    v.x += w.x; v.y += w.y; v.z += w.z; v.w += w.w;
                }
            }
            As[ak + 0][ar] = v.x; As[ak + 1][ar] = v.y;
            As[ak + 2][ar] = v.z; As[ak + 3][ar] = v.w;
        }
        // --- stage B tile into Bs[k][n] ---
        if (TRANS_B) {
            int c = col0 + ar;
            float4 v = make_float4(0.f, 0.f, 0.f, 0.f);
            if (c < Cc)
                v = *reinterpret_cast<const float4*>(&B[(long)c * ldb + k0 + ak]);
            Bs[ak + 0][ar] = v.x; Bs[ak + 1][ar] = v.y;
            Bs[ak + 2][ar] = v.z; Bs[ak + 3][ar] = v.w;
        } else {
            int bk = t >> 4;              // 0..15
            int bc = (t & 15) << 2;       // 0..60
            int c  = col0 + bc;
            float4 v = make_float4(0.f, 0.f, 0.f, 0.f);
            if (c < Cc)
                v = *reinterpret_cast<const float4*>(&B[(long)(k0 + bk) * ldb + c]);
            *reinterpret_cast<float4*>(&Bs[bk][bc]) = v;
        }
        __syncthreads();

        #pragma unroll
        for (int kk = 0; kk < 16; kk++) {
            float4 a4 = *reinterpret_cast<const float4*>(&As[kk][ty << 2]);
            float4 b4 = *reinterpret_cast<const float4*>(&Bs[kk][tx << 2]);
            float a[4] = {a4.x, a4.y, a4.z, a4.w};
            float b[4] = {b4.x, b4.y, b4.z, b4.w};
            #pragma unroll
            for (int i = 0; i < 4; i++)
                #pragma unroll
                for (int j = 0; j < 4; j++)
                    acc[i][j] = fmaf(a[i], b[j], acc[i][j]);
        }
        __syncthreads();
    }

    #pragma unroll
    for (int i = 0; i < 4; i++) {
        int r = row0 + (ty << 2) + i;
        if (r >= R) continue;
        #pragma unroll
        for (int j = 0; j < 4; j++) {
            int c = col0 + (tx << 2) + j;
            if (c >= Cc) continue;
            float v = acc[i][j] * alpha;
            if (bias) v += bias[c];
            if (ACT == 1) v = 0.5f * v * (1.0f + erff(v * 0.70710678118654752f));
            C[(long)r * ldc + c] = v;
        }
    }
}

// ---------------------------------------------------------------------------
// Inverse L2 norm of each memory row (m,b): mnorm[m*BSZ+b] = 1/||memory[m,b,:]||
// One warp per row, 8 rows per block.
// ---------------------------------------------------------------------------
__global__ void inv_norm_kernel(const float* __restrict__ mem, float* __restrict__ mnorm)
{
    int r    = blockIdx.x * 8 + (threadIdx.x >> 5);
    int lane = threadIdx.x & 31;
    const float* p = mem + (long)r * DIM;
    float s = 0.f;
    #pragma unroll
    for (int j = lane; j < DIM; j += 32) { float x = p[j]; s = fmaf(x, x, s); }
    #pragma unroll
    for (int o = 16; o; o >>= 1) s += __shfl_xor_sync(0xffffffffu, s, o);
    if (lane == 0) mnorm[r] = 1.0f / sqrtf(s);
}

// ---------------------------------------------------------------------------
// Top-32 of sim[b,n,:] * mnorm (per-m scale). Iterative argmax (32 passes),
// tie-break = lowest index (only the index SET matters downstream).
// Block = 256 threads, one block per (n,b). Row held in smem.
// ---------------------------------------------------------------------------
__global__ void topk_kernel(const float* __restrict__ sim,
                            const float* __restrict__ mnorm,
                            int* __restrict__ rns)
{
    int n = blockIdx.x, b = blockIdx.y;
    const float* row = sim + ((long)b * NP + n) * MNP;
    int t = threadIdx.x;
    __shared__ float sv[MNP];
    __shared__ float swv[8];
    __shared__ int   swi[8];
    __shared__ int   sbest;

    #pragma unroll
    for (int j = 0; j < MNP / 256; j++) {
        int m = t + j * 256;
        sv[m] = row[m] * mnorm[m * BSZ + b];
    }
    __syncthreads();

    int lane = t & 31, w = t >> 5;
    for (int it = 0; it < TOPK; it++) {
        float bv = -INFINITY; int bi = 0x7fffffff;
        #pragma unroll
        for (int j = 0; j < MNP / 256; j++) {
            int m = t + j * 256;
            float v = sv[m];
            if (v > bv || (v == bv && m < bi)) { bv = v; bi = m; }
        }
        #pragma unroll
        for (int o = 16; o; o >>= 1) {
            float ov = __shfl_xor_sync(0xffffffffu, bv, o);
            int   oi = __shfl_xor_sync(0xffffffffu, bi, o);
            if (ov > bv || (ov == bv && oi < bi)) { bv = ov; bi = oi; }
        }
        if (lane == 0) { swv[w] = bv; swi[w] = bi; }
        __syncthreads();
        if (t == 0) {
            float Bv = swv[0]; int Bi = swi[0];
            #pragma unroll
            for (int k = 1; k < 8; k++)
                if (swv[k] > Bv || (swv[k] == Bv && swi[k] < Bi)) { Bv = swv[k]; Bi = swi[k]; }
            sbest = Bi;
            rns[((long)b * NP + n) * TOPK + it] = Bi;
        }
        __syncthreads();
        if (t == 0) sv[sbest] = -INFINITY;
        __syncthreads();
    }
}

// ---------------------------------------------------------------------------
// Sparse cross-attention: per (n,b) block, one warp per head.
// softmax over exactly the TOPK selected keys (masked-out keys underflow to 0
// in fp32, identical to the reference's -1e9 masking).
// ---------------------------------------------------------------------------
__global__ void cross_attn_kernel(const float* __restrict__ Q,
                                  const float* __restrict__ Kb,
                                  const float* __restrict__ Vb,
                                  const int*   __restrict__ rns,
                                  float* __restrict__ cross)
{
    int n = blockIdx.x, b = blockIdx.y;
    int t = threadIdx.x, h = t >> 5, lane = t & 31;
    __shared__ int idx[TOPK];
    if (t < TOPK) idx[t] = rns[((long)b * NP + n) * TOPK + t];
    __syncthreads();

    long qoff = ((long)n * BSZ + b) * DIM + h * HD;
    float q = Q[qoff + lane];

    float myscore = -INFINITY;
    #pragma unroll
    for (int j = 0; j < TOPK; j++) {
        float prod = q * Kb[((long)idx[j] * BSZ + b) * DIM + h * HD + lane];
        #pragma unroll
        for (int o = 16; o; o >>= 1) prod += __shfl_xor_sync(0xffffffffu, prod, o);
        if (lane == j) myscore = prod * ATT_SCALE;
    }
    float mx = myscore;
    #pragma unroll
    for (int o = 16; o; o >>= 1) mx = fmaxf(mx, __shfl_xor_sync(0xffffffffu, mx, o));
    float e = expf(myscore - mx);
    float s = e;
    #pragma unroll
    for (int o = 16; o; o >>= 1) s += __shfl_xor_sync(0xffffffffu, s, o);
    float p = e / s;

    float acc = 0.f;
    #pragma unroll
    for (int j = 0; j < TOPK; j++) {
        float pj = __shfl_sync(0xffffffffu, p, j);
        acc = fmaf(pj, Vb[((long)idx[j] * BSZ + b) * DIM + h * HD + lane], acc);
    }
    cross[qoff + lane] = acc;
}

// ---------------------------------------------------------------------------
// out = LayerNorm(a + c) * w + beta   (row length = DIM = 256 = blockDim)
// ---------------------------------------------------------------------------
__global__ void add_ln_kernel(const float* __restrict__ a, const float* __restrict__ c,
                              const float* __restrict__ w, const float* __restrict__ beta,
                              float* __restrict__ out)
{
    long r = blockIdx.x;
    int  t = threadIdx.x;
    float x = a[r * DIM + t] + c[r * DIM + t];
    __shared__ float red[8];

    float s = x;
    #pragma unroll
    for (int o = 16; o; o >>= 1) s += __shfl_xor_sync(0xffffffffu, s, o);
    if ((t & 31) == 0) red[t >> 5] = s;
    __syncthreads();
    float tot = 0.f;
    #pragma unroll
    for (int k = 0; k < 8; k++) tot += red[k];
    float mu = tot * (1.0f / DIM);
    __syncthreads();

    float d  = x - mu;
    float s2 = d * d;
    #pragma unroll
    for (int o = 16; o; o >>= 1) s2 += __shfl_xor_sync(0xffffffffu, s2, o);
    if ((t & 31) == 0) red[t >> 5] = s2;
    __syncthreads();
    float tot2 = 0.f;
    #pragma unroll
    for (int k = 0; k < 8; k++) tot2 += red[k];
    float var = tot2 * (1.0f / DIM);

    out[r * DIM + t] = d * rsqrtf(var + LN_EPS) * w[t] + beta[t];
}

// ---------------------------------------------------------------------------
// In-place softmax over rows of length 512 (self-attention scores).
// ---------------------------------------------------------------------------
__global__ void softmax512_kernel(float* __restrict__ sc)
{
    long r = blockIdx.x;
    float* row = sc + r * 512;
    int t = threadIdx.x;
    float a = row[t], b = row[t + 256];
    __shared__ float red[8];

    float m = fmaxf(a, b);
    #pragma unroll
    for (int o = 16; o; o >>= 1) m = fmaxf(m, __shfl_xor_sync(0xffffffffu, m, o));
    if ((t & 31) == 0) red[t >> 5] = m;
    __syncthreads();
    float M = -INFINITY;
    #pragma unroll
    for (int k = 0; k < 8; k++) M = fmaxf(M, red[k]);
    __syncthreads();

    float ea = expf(a - M), eb = expf(b - M);
    float s = ea + eb;
    #pragma unroll
    for (int o = 16; o; o >>= 1) s += __shfl_xor_sync(0xffffffffu, s, o);
    if ((t & 31) == 0) red[t >> 5] = s;
    __syncthreads();
    float tot = 0.f;
    #pragma unroll
    for (int k = 0; k < 8; k++) tot += red[k];
    float inv = 1.0f / tot;
    row[t] = ea * inv;
    row[t + 256] = eb * inv;
}

// ---------------------------------------------------------------------------
// Launch
// ---------------------------------------------------------------------------
extern "C" void kernel_launch(void* const* d_in, const int* in_sizes, int n_in,
                              void* d_out, int out_size)
{
    const float* tgt      = (const float*)d_in[0];
    const float* memory   = (const float*)d_in[1];
    const float* qpos     = (const float*)d_in[2];
    const float* kpos     = (const float*)d_in[3];
    const float* cw1      = (const float*)d_in[4];
    const float* cb1      = (const float*)d_in[5];
    const float* cw2      = (const float*)d_in[6];
    const float* cb2      = (const float*)d_in[7];
    const float* cw3      = (const float*)d_in[8];
    const float* cb3      = (const float*)d_in[9];
    const float* sa_in_w  = (const float*)d_in[10];
    const float* sa_in_b  = (const float*)d_in[11];
    const float* sa_out_w = (const float*)d_in[12];
    const float* sa_out_b = (const float*)d_in[13];
    const float* ln1_w    = (const float*)d_in[14];
    const float* ln1_b    = (const float*)d_in[15];
    const float* ln2_w    = (const float*)d_in[16];
    const float* ln2_b    = (const float*)d_in[17];
    const float* ln3_w    = (const float*)d_in[18];
    const float* ln3_b    = (const float*)d_in[19];
    const float* ff1_w    = (const float*)d_in[20];
    const float* ff1_b    = (const float*)d_in[21];
    const float* ff2_w    = (const float*)d_in[22];
    const float* ff2_b    = (const float*)d_in[23];
    float* out = (float*)d_out;

    void *p;
    cudaGetSymbolAddress(&p, g_sim);   float* sim   = (float*)p;
    cudaGetSymbolAddress(&p, g_mnorm); float* mnorm = (float*)p;
    cudaGetSymbolAddress(&p, g_rns);   int*   rns   = (int*)p;
    cudaGetSymbolAddress(&p, g_K);     float* Kb    = (float*)p;
    cudaGetSymbolAddress(&p, g_V);     float* Vb    = (float*)p;
    cudaGetSymbolAddress(&p, g_Q);     float* Qb    = (float*)p;
    cudaGetSymbolAddress(&p, g_cross); float* cross = (float*)p;
    cudaGetSymbolAddress(&p, g_t1);    float* t1    = (float*)p;
    cudaGetSymbolAddress(&p, g_Q2);    float* Q2    = (float*)p;
    cudaGetSymbolAddress(&p, g_K2);    float* K2    = (float*)p;
    cudaGetSymbolAddress(&p, g_V2);    float* V2    = (float*)p;
    cudaGetSymbolAddress(&p, g_sc2);   float* sc2   = (float*)p;
    cudaGetSymbolAddress(&p, g_sa);    float* sa    = (float*)p;
    cudaGetSymbolAddress(&p, g_sa2);   float* sa2   = (float*)p;
    cudaGetSymbolAddress(&p, g_t2);    float* t2    = (float*)p;
    cudaGetSymbolAddress(&p, g_ffh);   float* ffh   = (float*)p;
    cudaGetSymbolAddress(&p, g_ffo);   float* ffo   = (float*)p;

    const long BD = (long)BSZ * DIM;   // 2048

    // 1) inverse norms of memory rows
    inv_norm_kernel<<<MNP * BSZ / 8, 256>>>(memory, mnorm);

    // 2) sim[b,n,m] = tgt[n,b,:] . memory[m,b,:]   (x-norm dropped: order-preserving)
    sgemm_kernel<true, 0><<<dim3(MNP / 64, NP / 64, BSZ), 256>>>(
        tgt, nullptr, memory, nullptr, sim,
        NP, MNP, DIM, BD, BD, MNP,
        0, DIM, 0, DIM, 0, (long)NP * MNP, BSZ, 1.0f);

    // 3) top-32 indices per (b,n)
    topk_kernel<<<dim3(NP, BSZ), 256>>>(sim, mnorm, rns);

    // 4) projections: K = (memory+kpos)@cw2^T+cb2 ; V = memory@cw3^T+cb3 ; Q = (tgt+qpos)@cw1^T+cb1
    sgemm_kernel<true, 0><<<dim3(DIM / 64, MNP * BSZ / 64, 1), 256>>>(
        memory, kpos, cw2, cb2, Kb,
        MNP * BSZ, DIM, DIM, DIM, DIM, DIM, 0, 0, 0, 0, 0, 0, 1, 1.0f);
    sgemm_kernel<true, 0><<<dim3(DIM / 64, MNP * BSZ / 64, 1), 256>>>(
        memory, nullptr, cw3, cb3, Vb,
        MNP * BSZ, DIM, DIM, DIM, DIM, DIM, 0, 0, 0, 0, 0, 0, 1, 1.0f);
    sgemm_kernel<true, 0><<<dim3(DIM / 64, NP * BSZ / 64, 1), 256>>>(
        tgt, qpos, cw1, cb1, Qb,
        NP * BSZ, DIM, DIM, DIM, DIM, DIM, 0, 0, 0, 0, 0, 0, 1, 1.0f);

    // 5) sparse cross-attention + 6) t1 = LN(tgt + cross)
    cross_attn_kernel<<<dim3(NP, BSZ), 256>>>(Qb, Kb, Vb, rns, cross);
    add_ln_kernel<<<NP * BSZ, 256>>>(tgt, cross, ln1_w, ln1_b, t1);

    // 7) self-attn projections
    sgemm_kernel<true, 0><<<dim3(DIM / 64, NP * BSZ / 64, 1), 256>>>(
        t1, qpos, sa_in_w, sa_in_b, Q2,
        NP * BSZ, DIM, DIM, DIM, DIM, DIM, 0, 0, 0, 0, 0, 0, 1, 1.0f);
    sgemm_kernel<true, 0><<<dim3(DIM / 64, NP * BSZ / 64, 1), 256>>>(
        t1, qpos, sa_in_w + DIM * DIM, sa_in_b + DIM, K2,
        NP * BSZ, DIM, DIM, DIM, DIM, DIM, 0, 0, 0, 0, 0, 0, 1, 1.0f);
    sgemm_kernel<true, 0><<<dim3(DIM / 64, NP * BSZ / 64, 1), 256>>>(
        t1, nullptr, sa_in_w + 2 * DIM * DIM, sa_in_b + 2 * DIM, V2,
        NP * BSZ, DIM, DIM, DIM, DIM, DIM, 0, 0, 0, 0, 0, 0, 1, 1.0f);

    // 8) scores[b,h,n,m] = scale * Q2 . K2   (batched over (b,h))
    sgemm_kernel<true, 0><<<dim3(NP / 64, NP / 64, BSZ * NH), 256>>>(
        Q2, nullptr, K2, nullptr, sc2,
        NP, NP, HD, (int)BD, (int)BD, NP,
        DIM, HD, DIM, HD, (long)NH * NP * NP, (long)NP * NP, NH, ATT_SCALE);

    // 9) softmax over keys
    softmax512_kernel<<<BSZ * NH * NP, 256>>>(sc2);

    // 10) sa[b,h,n,d] = P @ V2  (NN), written directly into (n,b,dim) layout
    sgemm_kernel<false, 0><<<dim3(1, NP / 64, BSZ * NH), 256>>>(
        sc2, nullptr, V2, nullptr, sa,
        NP, HD, NP, NP, (int)BD, (int)BD,
        (long)NH * NP * NP, (long)NP * NP, DIM, HD, DIM, HD, NH, 1.0f);

    // 11) out projection + 12) t2 = LN(t1 + sa2)
    sgemm_kernel<true, 0><<<dim3(DIM / 64, NP * BSZ / 64, 1), 256>>>(
        sa, nullptr, sa_out_w, sa_out_b, sa2,
        NP * BSZ, DIM, DIM, DIM, DIM, DIM, 0, 0, 0, 0, 0, 0, 1, 1.0f);
    add_ln_kernel<<<NP * BSZ, 256>>>(t1, sa2, ln2_w, ln2_b, t2);

    // 13) FFN: gelu(t2@ff1^T+b1) @ ff2^T + b2 ; out = LN(t2 + ff)
    sgemm_kernel<true, 1><<<dim3(FF / 64, NP * BSZ / 64, 1), 256>>>(
        t2, nullptr, ff1_w, ff1_b, ffh,
        NP * BSZ, FF, DIM, DIM, DIM, FF, 0, 0, 0, 0, 0, 0, 1, 1.0f);
    sgemm_kernel<true, 0><<<dim3(DIM / 64, NP * BSZ / 64, 1), 256>>>(
        ffh, nullptr, ff2_w, ff2_b, ffo,
        NP * BSZ, DIM, FF, FF, FF, DIM, 0, 0, 0, 0, 0, 0, 1, 1.0f);
    add_ln_kernel<<<NP * BSZ, 256>>>(t2, ffo, ln3_w, ln3_b, out);
}

// round 3
// speedup vs baseline: 1.5762x; 1.5762x over previous
#include <cuda_runtime.h>
#include <cuda_bf16.h>
#include <math.h>
#include <stdint.h>

#define NP   512
#define MNP  4096
#define BSZ  8
#define DIM  256
#define NH   8
#define TOPK 32
#define FF   2048
#define HD   32
#define LN_EPS 1e-5f
#define ATT_SCALE 0.17677669529663687f   /* 1/sqrt(32) */

// ---------------------------------------------------------------------------
// Scratch (device globals: allocation-free per harness rules)
// ---------------------------------------------------------------------------
__device__ float g_sim   [BSZ * NP * MNP];
__device__ float g_mnorm [MNP * BSZ];
__device__ int   g_rns   [BSZ * NP * TOPK];
__device__ float g_K     [MNP * BSZ * DIM];
__device__ float g_V     [MNP * BSZ * DIM];
__device__ float g_Q     [NP * BSZ * DIM];
__device__ float g_cross [NP * BSZ * DIM];
__device__ float g_t1    [NP * BSZ * DIM];
__device__ float g_QK2   [NP * BSZ * 2 * DIM];
__device__ float g_V2    [NP * BSZ * DIM];
__device__ float g_sc2   [BSZ * NH * NP * NP];
__device__ float g_sa    [NP * BSZ * DIM];
__device__ float g_sa2   [NP * BSZ * DIM];
__device__ float g_t2    [NP * BSZ * DIM];
__device__ float g_ffh   [NP * BSZ * FF];
__device__ float g_ffo   [NP * BSZ * DIM];

__device__ __forceinline__ float ftf32(float x) {
    uint32_t u;
    asm("cvt.rna.tf32.f32 %0, %1;" : "=r"(u) : "f"(x));
    return __uint_as_float(u);
}

// ---------------------------------------------------------------------------
// EXACT fp32 FFMA SGEMM (NT) — used ONLY for the sim GEMM feeding top-k.
// C[z] = A . B^T, A:(R,K) lda w/ offset z*sA2, B:(Cc,K) ldb w/ offset z*sB2,
// C offset z*sC2. Tiles 64x64x16, 256 thr, 4x4 microtile.
// ---------------------------------------------------------------------------
__global__ void sim_sgemm_kernel(
    const float* __restrict__ A, const float* __restrict__ B,
    float* __restrict__ C,
    int R, int Cc, int K, int lda, int ldb, int ldc,
    long sA2, long sB2, long sC2)
{
    __shared__ float As[16][64];
    __shared__ float Bs[16][64];

    const int z = blockIdx.z;
    A += z * sA2; B += z * sB2; C += z * sC2;

    const int row0 = blockIdx.y * 64;
    const int col0 = blockIdx.x * 64;
    const int t  = threadIdx.x;
    const int tx = t & 15, ty = t >> 4;
    const int ar = t >> 2;
    const int ak = (t & 3) << 2;

    float acc[4][4] = {};

    for (int k0 = 0; k0 < K; k0 += 16) {
        {
            int r = row0 + ar;
            float4 v = *reinterpret_cast<const float4*>(&A[(long)r * lda + k0 + ak]);
            As[ak + 0][ar] = v.x; As[ak + 1][ar] = v.y;
            As[ak + 2][ar] = v.z; As[ak + 3][ar] = v.w;
        }
        {
            int c = col0 + ar;
            float4 v = *reinterpret_cast<const float4*>(&B[(long)c * ldb + k0 + ak]);
            Bs[ak + 0][ar] = v.x; Bs[ak + 1][ar] = v.y;
            Bs[ak + 2][ar] = v.z; Bs[ak + 3][ar] = v.w;
        }
        __syncthreads();

        #pragma unroll
        for (int kk = 0; kk < 16; kk++) {
            float4 a4 = *reinterpret_cast<const float4*>(&As[kk][ty << 2]);
            float4 b4 = *reinterpret_cast<const float4*>(&Bs[kk][tx << 2]);
            float a[4] = {a4.x, a4.y, a4.z, a4.w};
            float b[4] = {b4.x, b4.y, b4.z, b4.w};
            #pragma unroll
            for (int i = 0; i < 4; i++)
                #pragma unroll
                for (int j = 0; j < 4; j++)
                    acc[i][j] = fmaf(a[i], b[j], acc[i][j]);
        }
        __syncthreads();
    }

    #pragma unroll
    for (int i = 0; i < 4; i++) {
        int r = row0 + (ty << 2) + i;
        #pragma unroll
        for (int j = 0; j < 4; j++) {
            int c = col0 + (tx << 2) + j;
            C[(long)r * ldc + c] = acc[i][j];
        }
    }
}

// ---------------------------------------------------------------------------
// TF32 tensor-core batched GEMM: C = act(alpha * (A (+A2)) @ op(B) + bias)
// Tile: 128 x BN x 32. 256 threads (8 warps). mma.sync m16n8k8 tf32.
// ---------------------------------------------------------------------------
template<int BN, bool TRANS_B, int ACT>
__global__ void tgemm_kernel(
    const float* __restrict__ A, const float* __restrict__ A2,
    const float* __restrict__ B, const float* __restrict__ bias,
    float* __restrict__ C,
    int R, int Cc, int K,
    int lda, int ldb, int ldc,
    long sA1, long sA2, long sB1, long sB2, long sC1, long sC2,
    int Z2, float alpha)
{
    constexpr int BM = 128, BK = 32, LDS = BK + 4;
    constexpr int WARPS_N = (BN == 64) ? 2 : 1;
    constexpr int WARPS_M = 8 / WARPS_N;
    constexpr int WM = BM / WARPS_M;
    constexpr int WN = BN / WARPS_N;
    constexpr int MT = WM / 16;
    constexpr int NT = WN / 8;

    __shared__ float As[BM * LDS];
    __shared__ float Bs[BN * LDS];

    const int z  = blockIdx.z;
    const int z1 = z / Z2, z2 = z % Z2;
    A += z1 * sA1 + z2 * sA2;
    if (A2) A2 += z1 * sA1 + z2 * sA2;
    B += z1 * sB1 + z2 * sB2;
    C += z1 * sC1 + z2 * sC2;

    const int row0 = blockIdx.y * BM;
    const int col0 = blockIdx.x * BN;
    const int t    = threadIdx.x;
    const int lane = t & 31, wid = t >> 5;
    const int wm = wid % WARPS_M, wn = wid / WARPS_M;

    float4 aR[4];
    float4 bRt[(BN == 64) ? 2 : 1];
    float  bRn[BN / 8];

    const int arow = t >> 3;
    const int acol = (t & 7) << 2;

    auto loadA = [&](int k0) {
        #pragma unroll
        for (int i = 0; i < 4; i++) {
            int r = row0 + arow + i * 32;
            float4 v = make_float4(0.f, 0.f, 0.f, 0.f);
            if (r < R) {
                v = *reinterpret_cast<const float4*>(&A[(long)r * lda + k0 + acol]);
                if (A2) {
                    float4 w = *reinterpret_cast<const float4*>(&A2[(long)r * lda + k0 + acol]);
                    v.x += w.x; v.y += w.y; v.z += w.z; v.w += w.w;
                }
            }
            aR[i] = v;
        }
    };
    auto loadB = [&](int k0) {
        if constexpr (TRANS_B) {
            #pragma unroll
            for (int i = 0; i < BN / 32; i++) {
                int c = col0 + arow + i * 32;
                float4 v = make_float4(0.f, 0.f, 0.f, 0.f);
                if (c < Cc)
                    v = *reinterpret_cast<const float4*>(&B[(long)c * ldb + k0 + acol]);
                bRt[i] = v;
            }
        } else {
            #pragma unroll
            for (int i = 0; i < BN / 8; i++) {
                int e = t + i * 256;
                int n = e & (BN - 1);
                int k = e / BN;
                float v = 0.f;
                if (col0 + n < Cc)
                    v = B[(long)(k0 + k) * ldb + col0 + n];
                bRn[i] = v;
            }
        }
    };
    auto storeStage = [&]() {
        #pragma unroll
        for (int i = 0; i < 4; i++) {
            float4 v = aR[i];
            v.x = ftf32(v.x); v.y = ftf32(v.y); v.z = ftf32(v.z); v.w = ftf32(v.w);
            *reinterpret_cast<float4*>(&As[(arow + i * 32) * LDS + acol]) = v;
        }
        if constexpr (TRANS_B) {
            #pragma unroll
            for (int i = 0; i < BN / 32; i++) {
                float4 v = bRt[i];
                v.x = ftf32(v.x); v.y = ftf32(v.y); v.z = ftf32(v.z); v.w = ftf32(v.w);
                *reinterpret_cast<float4*>(&Bs[(arow + i * 32) * LDS + acol]) = v;
            }
        } else {
            #pragma unroll
            for (int i = 0; i < BN / 8; i++) {
                int e = t + i * 256;
                int n = e & (BN - 1);
                int k = e / BN;
                Bs[n * LDS + k] = ftf32(bRn[i]);
            }
        }
    };

    float accs[MT][NT][4];
    #pragma unroll
    for (int mt = 0; mt < MT; mt++)
        #pragma unroll
        for (int nt = 0; nt < NT; nt++)
            #pragma unroll
            for (int i = 0; i < 4; i++) accs[mt][nt][i] = 0.f;

    const uint32_t* asp = reinterpret_cast<const uint32_t*>(As);
    const uint32_t* bsp = reinterpret_cast<const uint32_t*>(Bs);

    auto compute = [&]() {
        #pragma unroll
        for (int ks = 0; ks < 4; ks++) {
            uint32_t af[MT][4], bf[NT][2];
            #pragma unroll
            for (int mt = 0; mt < MT; mt++) {
                int rb = wm * WM + mt * 16 + (lane >> 2);
                int cb = ks * 8 + (lane & 3);
                af[mt][0] = asp[rb * LDS + cb];
                af[mt][1] = asp[(rb + 8) * LDS + cb];
                af[mt][2] = asp[rb * LDS + cb + 4];
                af[mt][3] = asp[(rb + 8) * LDS + cb + 4];
            }
            #pragma unroll
            for (int nt = 0; nt < NT; nt++) {
                int nb = wn * WN + nt * 8 + (lane >> 2);
                int kb = ks * 8 + (lane & 3);
                bf[nt][0] = bsp[nb * LDS + kb];
                bf[nt][1] = bsp[nb * LDS + kb + 4];
            }
            #pragma unroll
            for (int mt = 0; mt < MT; mt++)
                #pragma unroll
                for (int nt = 0; nt < NT; nt++) {
                    float* c = accs[mt][nt];
                    asm volatile(
                        "mma.sync.aligned.m16n8k8.row.col.f32.tf32.tf32.f32 "
                        "{%0,%1,%2,%3}, {%4,%5,%6,%7}, {%8,%9}, {%0,%1,%2,%3};"
                        : "+f"(c[0]), "+f"(c[1]), "+f"(c[2]), "+f"(c[3])
                        : "r"(af[mt][0]), "r"(af[mt][1]), "r"(af[mt][2]), "r"(af[mt][3]),
                          "r"(bf[nt][0]), "r"(bf[nt][1]));
                }
        }
    };

    loadA(0); loadB(0);
    int k0 = 0;
    for (;;) {
        storeStage();
        __syncthreads();
        k0 += BK;
        bool more = (k0 < K);
        if (more) { loadA(k0); loadB(k0); }
        compute();
        if (!more) break;
        __syncthreads();
    }

    #pragma unroll
    for (int mt = 0; mt < MT; mt++) {
        #pragma unroll
        for (int nt = 0; nt < NT; nt++) {
            int r = row0 + wm * WM + mt * 16 + (lane >> 2);
            int c = col0 + wn * WN + nt * 8 + ((lane & 3) << 1);
            float* acc = accs[mt][nt];
            #pragma unroll
            for (int e = 0; e < 4; e++) {
                int rr = r + (e >> 1) * 8;
                int cc = c + (e & 1);
                if (rr >= R || cc >= Cc) continue;
                float v = acc[e] * alpha;
                if (bias) v += bias[cc];
                if (ACT == 1) v = 0.5f * v * (1.0f + erff(v * 0.70710678118654752f));
                C[(long)rr * ldc + cc] = v;
            }
        }
    }
}

// ---------------------------------------------------------------------------
// Inverse L2 norm of each memory row (m,b)
// ---------------------------------------------------------------------------
__global__ void inv_norm_kernel(const float* __restrict__ mem, float* __restrict__ mnorm)
{
    int r    = blockIdx.x * 8 + (threadIdx.x >> 5);
    int lane = threadIdx.x & 31;
    const float* p = mem + (long)r * DIM;
    float s = 0.f;
    #pragma unroll
    for (int j = lane; j < DIM; j += 32) { float x = p[j]; s = fmaf(x, x, s); }
    #pragma unroll
    for (int o = 16; o; o >>= 1) s += __shfl_xor_sync(0xffffffffu, s, o);
    if (lane == 0) mnorm[r] = 1.0f / sqrtf(s);
}

// ---------------------------------------------------------------------------
// Top-32 of sim[b,n,:] * mnorm. Iterative argmax, lowest-index tie-break.
// ---------------------------------------------------------------------------
__global__ void topk_kernel(const float* __restrict__ sim,
                            const float* __restrict__ mnorm,
                            int* __restrict__ rns)
{
    int n = blockIdx.x, b = blockIdx.y;
    const float* row = sim + ((long)b * NP + n) * MNP;
    int t = threadIdx.x;
    __shared__ float sv[MNP];
    __shared__ float swv[8];
    __shared__ int   swi[8];
    __shared__ int   sbest;

    #pragma unroll
    for (int j = 0; j < MNP / 256; j++) {
        int m = t + j * 256;
        sv[m] = row[m] * mnorm[m * BSZ + b];
    }
    __syncthreads();

    int lane = t & 31, w = t >> 5;
    for (int it = 0; it < TOPK; it++) {
        float bv = -INFINITY; int bi = 0x7fffffff;
        #pragma unroll
        for (int j = 0; j < MNP / 256; j++) {
            int m = t + j * 256;
            float v = sv[m];
            if (v > bv || (v == bv && m < bi)) { bv = v; bi = m; }
        }
        #pragma unroll
        for (int o = 16; o; o >>= 1) {
            float ov = __shfl_xor_sync(0xffffffffu, bv, o);
            int   oi = __shfl_xor_sync(0xffffffffu, bi, o);
            if (ov > bv || (ov == bv && oi < bi)) { bv = ov; bi = oi; }
        }
        if (lane == 0) { swv[w] = bv; swi[w] = bi; }
        __syncthreads();
        if (t == 0) {
            float Bv = swv[0]; int Bi = swi[0];
            #pragma unroll
            for (int k = 1; k < 8; k++)
                if (swv[k] > Bv || (swv[k] == Bv && swi[k] < Bi)) { Bv = swv[k]; Bi = swi[k]; }
            sbest = Bi;
            rns[((long)b * NP + n) * TOPK + it] = Bi;
        }
        __syncthreads();
        if (t == 0) sv[sbest] = -INFINITY;
        __syncthreads();
    }
}

// ---------------------------------------------------------------------------
// Sparse cross-attention: one warp per head, softmax over TOPK keys.
// ---------------------------------------------------------------------------
__global__ void cross_attn_kernel(const float* __restrict__ Q,
                                  const float* __restrict__ Kb,
                                  const float* __restrict__ Vb,
                                  const int*   __restrict__ rns,
                                  float* __restrict__ cross)
{
    int n = blockIdx.x, b = blockIdx.y;
    int t = threadIdx.x, h = t >> 5, lane = t & 31;
    __shared__ int idx[TOPK];
    if (t < TOPK) idx[t] = rns[((long)b * NP + n) * TOPK + t];
    __syncthreads();

    long qoff = ((long)n * BSZ + b) * DIM + h * HD;
    float q = Q[qoff + lane];

    float myscore = -INFINITY;
    #pragma unroll
    for (int j = 0; j < TOPK; j++) {
        float prod = q * Kb[((long)idx[j] * BSZ + b) * DIM + h * HD + lane];
        #pragma unroll
        for (int o = 16; o; o >>= 1) prod += __shfl_xor_sync(0xffffffffu, prod, o);
        if (lane == j) myscore = prod * ATT_SCALE;
    }
    float mx = myscore;
    #pragma unroll
    for (int o = 16; o; o >>= 1) mx = fmaxf(mx, __shfl_xor_sync(0xffffffffu, mx, o));
    float e = expf(myscore - mx);
    float s = e;
    #pragma unroll
    for (int o = 16; o; o >>= 1) s += __shfl_xor_sync(0xffffffffu, s, o);
    float p = e / s;

    float acc = 0.f;
    #pragma unroll
    for (int j = 0; j < TOPK; j++) {
        float pj = __shfl_sync(0xffffffffu, p, j);
        acc = fmaf(pj, Vb[((long)idx[j] * BSZ + b) * DIM + h * HD + lane], acc);
    }
    cross[qoff + lane] = acc;
}

// ---------------------------------------------------------------------------
// out = LayerNorm(a + c) * w + beta
// ---------------------------------------------------------------------------
__global__ void add_ln_kernel(const float* __restrict__ a, const float* __restrict__ c,
                              const float* __restrict__ w, const float* __restrict__ beta,
                              float* __restrict__ out)
{
    long r = blockIdx.x;
    int  t = threadIdx.x;
    float x = a[r * DIM + t] + c[r * DIM + t];
    __shared__ float red[8];

    float s = x;
    #pragma unroll
    for (int o = 16; o; o >>= 1) s += __shfl_xor_sync(0xffffffffu, s, o);
    if ((t & 31) == 0) red[t >> 5] = s;
    __syncthreads();
    float tot = 0.f;
    #pragma unroll
    for (int k = 0; k < 8; k++) tot += red[k];
    float mu = tot * (1.0f / DIM);
    __syncthreads();

    float d  = x - mu;
    float s2 = d * d;
    #pragma unroll
    for (int o = 16; o; o >>= 1) s2 += __shfl_xor_sync(0xffffffffu, s2, o);
    if ((t & 31) == 0) red[t >> 5] = s2;
    __syncthreads();
    float tot2 = 0.f;
    #pragma unroll
    for (int k = 0; k < 8; k++) tot2 += red[k];
    float var = tot2 * (1.0f / DIM);

    out[r * DIM + t] = d * rsqrtf(var + LN_EPS) * w[t] + beta[t];
}

// ---------------------------------------------------------------------------
// In-place softmax over rows of length 512
// ---------------------------------------------------------------------------
__global__ void softmax512_kernel(float* __restrict__ sc)
{
    long r = blockIdx.x;
    float* row = sc + r * 512;
    int t = threadIdx.x;
    float a = row[t], b = row[t + 256];
    __shared__ float red[8];

    float m = fmaxf(a, b);
    #pragma unroll
    for (int o = 16; o; o >>= 1) m = fmaxf(m, __shfl_xor_sync(0xffffffffu, m, o));
    if ((t & 31) == 0) red[t >> 5] = m;
    __syncthreads();
    float M = -INFINITY;
    #pragma unroll
    for (int k = 0; k < 8; k++) M = fmaxf(M, red[k]);
    __syncthreads();

    float ea = expf(a - M), eb = expf(b - M);
    float s = ea + eb;
    #pragma unroll
    for (int o = 16; o; o >>= 1) s += __shfl_xor_sync(0xffffffffu, s, o);
    if ((t & 31) == 0) red[t >> 5] = s;
    __syncthreads();
    float tot = 0.f;
    #pragma unroll
    for (int k = 0; k < 8; k++) tot += red[k];
    float inv = 1.0f / tot;
    row[t] = ea * inv;
    row[t + 256] = eb * inv;
}

// ---------------------------------------------------------------------------
// Launch
// ---------------------------------------------------------------------------
extern "C" void kernel_launch(void* const* d_in, const int* in_sizes, int n_in,
                              void* d_out, int out_size)
{
    const float* tgt      = (const float*)d_in[0];
    const float* memory   = (const float*)d_in[1];
    const float* qpos     = (const float*)d_in[2];
    const float* kpos     = (const float*)d_in[3];
    const float* cw1      = (const float*)d_in[4];
    const float* cb1      = (const float*)d_in[5];
    const float* cw2      = (const float*)d_in[6];
    const float* cb2      = (const float*)d_in[7];
    const float* cw3      = (const float*)d_in[8];
    const float* cb3      = (const float*)d_in[9];
    const float* sa_in_w  = (const float*)d_in[10];
    const float* sa_in_b  = (const float*)d_in[11];
    const float* sa_out_w = (const float*)d_in[12];
    const float* sa_out_b = (const float*)d_in[13];
    const float* ln1_w    = (const float*)d_in[14];
    const float* ln1_b    = (const float*)d_in[15];
    const float* ln2_w    = (const float*)d_in[16];
    const float* ln2_b    = (const float*)d_in[17];
    const float* ln3_w    = (const float*)d_in[18];
    const float* ln3_b    = (const float*)d_in[19];
    const float* ff1_w    = (const float*)d_in[20];
    const float* ff1_b    = (const float*)d_in[21];
    const float* ff2_w    = (const float*)d_in[22];
    const float* ff2_b    = (const float*)d_in[23];
    float* out = (float*)d_out;

    void *p;
    cudaGetSymbolAddress(&p, g_sim);   float* sim   = (float*)p;
    cudaGetSymbolAddress(&p, g_mnorm); float* mnorm = (float*)p;
    cudaGetSymbolAddress(&p, g_rns);   int*   rns   = (int*)p;
    cudaGetSymbolAddress(&p, g_K);     float* Kb    = (float*)p;
    cudaGetSymbolAddress(&p, g_V);     float* Vb    = (float*)p;
    cudaGetSymbolAddress(&p, g_Q);     float* Qb    = (float*)p;
    cudaGetSymbolAddress(&p, g_cross); float* cross = (float*)p;
    cudaGetSymbolAddress(&p, g_t1);    float* t1    = (float*)p;
    cudaGetSymbolAddress(&p, g_QK2);   float* QK2   = (float*)p;
    cudaGetSymbolAddress(&p, g_V2);    float* V2    = (float*)p;
    cudaGetSymbolAddress(&p, g_sc2);   float* sc2   = (float*)p;
    cudaGetSymbolAddress(&p, g_sa);    float* sa    = (float*)p;
    cudaGetSymbolAddress(&p, g_sa2);   float* sa2   = (float*)p;
    cudaGetSymbolAddress(&p, g_t2);    float* t2    = (float*)p;
    cudaGetSymbolAddress(&p, g_ffh);   float* ffh   = (float*)p;
    cudaGetSymbolAddress(&p, g_ffo);   float* ffo   = (float*)p;

    const long BD = (long)BSZ * DIM;   // 2048

    // 1) inverse norms of memory rows
    inv_norm_kernel<<<MNP * BSZ / 8, 256>>>(memory, mnorm);

    // 2) sim[b,n,m] = tgt[n,b,:] . memory[m,b,:]  — EXACT fp32 (feeds top-k)
    sim_sgemm_kernel<<<dim3(MNP / 64, NP / 64, BSZ), 256>>>(
        tgt, memory, sim,
        NP, MNP, DIM, (int)BD, (int)BD, MNP,
        DIM, DIM, (long)NP * MNP);

    // 3) top-32 indices
    topk_kernel<<<dim3(NP, BSZ), 256>>>(sim, mnorm, rns);

    // 4) cross projections (TF32)
    tgemm_kernel<64, true, 0><<<dim3(DIM / 64, MNP * BSZ / 128, 1), 256>>>(
        memory, kpos, cw2, cb2, Kb,
        MNP * BSZ, DIM, DIM, DIM, DIM, DIM, 0, 0, 0, 0, 0, 0, 1, 1.0f);
    tgemm_kernel<64, true, 0><<<dim3(DIM / 64, MNP * BSZ / 128, 1), 256>>>(
        memory, nullptr, cw3, cb3, Vb,
        MNP * BSZ, DIM, DIM, DIM, DIM, DIM, 0, 0, 0, 0, 0, 0, 1, 1.0f);
    tgemm_kernel<64, true, 0><<<dim3(DIM / 64, NP * BSZ / 128, 1), 256>>>(
        tgt, qpos, cw1, cb1, Qb,
        NP * BSZ, DIM, DIM, DIM, DIM, DIM, 0, 0, 0, 0, 0, 0, 1, 1.0f);

    // 5) sparse cross-attention, 6) t1 = LN(tgt + cross)
    cross_attn_kernel<<<dim3(NP, BSZ), 256>>>(Qb, Kb, Vb, rns, cross);
    add_ln_kernel<<<NP * BSZ, 256>>>(tgt, cross, ln1_w, ln1_b, t1);

    // 7) self-attn projections: Q2|K2 fused (Cc=512), V2 separate
    tgemm_kernel<64, true, 0><<<dim3(2 * DIM / 64, NP * BSZ / 128, 1), 256>>>(
        t1, qpos, sa_in_w, sa_in_b, QK2,
        NP * BSZ, 2 * DIM, DIM, DIM, DIM, 2 * DIM, 0, 0, 0, 0, 0, 0, 1, 1.0f);
    tgemm_kernel<64, true, 0><<<dim3(DIM / 64, NP * BSZ / 128, 1), 256>>>(
        t1, nullptr, sa_in_w + 2 * DIM * DIM, sa_in_b + 2 * DIM, V2,
        NP * BSZ, DIM, DIM, DIM, DIM, DIM, 0, 0, 0, 0, 0, 0, 1, 1.0f);

    // 8) scores[b,h,n,m] = scale * Q2 . K2
    tgemm_kernel<64, true, 0><<<dim3(NP / 64, NP / 128, BSZ * NH), 256>>>(
        QK2, nullptr, QK2 + DIM, nullptr, sc2,
        NP, NP, HD, (int)(BSZ * 2 * DIM), (int)(BSZ * 2 * DIM), NP,
        2 * DIM, HD, 2 * DIM, HD, (long)NH * NP * NP, (long)NP * NP, NH, ATT_SCALE);

    // 9) softmax over keys
    softmax512_kernel<<<BSZ * NH * NP, 256>>>(sc2);

    // 10) sa = P @ V2 (NN), BN=32 tile
    tgemm_kernel<32, false, 0><<<dim3(1, NP / 128, BSZ * NH), 256>>>(
        sc2, nullptr, V2, nullptr, sa,
        NP, HD, NP, NP, (int)BD, (int)BD,
        (long)NH * NP * NP, (long)NP * NP, DIM, HD, DIM, HD, NH, 1.0f);

    // 11) out projection, 12) t2 = LN(t1 + sa2)
    tgemm_kernel<64, true, 0><<<dim3(DIM / 64, NP * BSZ / 128, 1), 256>>>(
        sa, nullptr, sa_out_w, sa_out_b, sa2,
        NP * BSZ, DIM, DIM, DIM, DIM, DIM, 0, 0, 0, 0, 0, 0, 1, 1.0f);
    add_ln_kernel<<<NP * BSZ, 256>>>(t1, sa2, ln2_w, ln2_b, t2);

    // 13) FFN + final LN
    tgemm_kernel<64, true, 1><<<dim3(FF / 64, NP * BSZ / 128, 1), 256>>>(
        t2, nullptr, ff1_w, ff1_b, ffh,
        NP * BSZ, FF, DIM, DIM, DIM, FF, 0, 0, 0, 0, 0, 0, 1, 1.0f);
    tgemm_kernel<64, true, 0><<<dim3(DIM / 64, NP * BSZ / 128, 1), 256>>>(
        ffh, nullptr, ff2_w, ff2_b, ffo,
        NP * BSZ, DIM, FF, FF, FF, DIM, 0, 0, 0, 0, 0, 0, 1, 1.0f);
    add_ln_kernel<<<NP * BSZ, 256>>>(t2, ffo, ln3_w, ln3_b, out);
}

// round 4
// speedup vs baseline: 1.6404x; 1.0407x over previous
#include <cuda_runtime.h>
#include <cuda_bf16.h>
#include <math.h>
#include <stdint.h>

#define NP   512
#define MNP  4096
#define BSZ  8
#define DIM  256
#define NH   8
#define TOPK 32
#define FF   2048
#define HD   32
#define LN_EPS 1e-5f
#define ATT_SCALE 0.17677669529663687f   /* 1/sqrt(32) */

// ---------------------------------------------------------------------------
// Scratch (device globals)
// ---------------------------------------------------------------------------
__device__ float g_sim   [BSZ * NP * MNP];
__device__ float g_mnorm [MNP * BSZ];
__device__ int   g_rns   [BSZ * NP * TOPK];
__device__ float g_K     [MNP * BSZ * DIM];
__device__ float g_V     [MNP * BSZ * DIM];
__device__ float g_Q     [NP * BSZ * DIM];
__device__ float g_cross [NP * BSZ * DIM];
__device__ float g_t1    [NP * BSZ * DIM];
__device__ float g_QK2   [NP * BSZ * 2 * DIM];
__device__ float g_V2    [NP * BSZ * DIM];
__device__ float g_sc2   [BSZ * NH * NP * NP];
__device__ float g_sa    [NP * BSZ * DIM];
__device__ float g_sa2   [NP * BSZ * DIM];
__device__ float g_t2    [NP * BSZ * DIM];
__device__ float g_ffh   [NP * BSZ * FF];
__device__ float g_ffo   [NP * BSZ * DIM];
__device__ float g_madd  [MNP * BSZ * DIM];   // memory + kpos
__device__ float g_qadd  [NP * BSZ * DIM];    // tgt+qpos / t1+qpos (reused)

__device__ __forceinline__ float ftf32(float x) {
    uint32_t u;
    asm("cvt.rna.tf32.f32 %0, %1;" : "=r"(u) : "f"(x));
    return __uint_as_float(u);
}

__device__ __forceinline__ void cpa16(uint32_t dst, const float* src) {
    asm volatile("cp.async.cg.shared.global [%0], [%1], 16;" :: "r"(dst), "l"(src));
}

// ---------------------------------------------------------------------------
// Elementwise o = a + b (float4)
// ---------------------------------------------------------------------------
__global__ void vecadd_kernel(const float* __restrict__ a, const float* __restrict__ b,
                              float* __restrict__ o, int n4)
{
    int i = blockIdx.x * blockDim.x + threadIdx.x;
    if (i < n4) {
        float4 x = ((const float4*)a)[i];
        float4 y = ((const float4*)b)[i];
        x.x += y.x; x.y += y.y; x.z += y.z; x.w += y.w;
        ((float4*)o)[i] = x;
    }
}

// ---------------------------------------------------------------------------
// EXACT fp32 FFMA SGEMM (NT) for the sim GEMM feeding top-k.
// 128x128x16 tiles, 256 threads, 8x8 microtile. Dims must divide tiles.
// ---------------------------------------------------------------------------
__global__ void __launch_bounds__(256) sim_sgemm2(
    const float* __restrict__ A, const float* __restrict__ B, float* __restrict__ C,
    int K, int lda, int ldb, int ldc, long sA2, long sB2, long sC2)
{
    constexpr int BK = 16, PP = 132;   // As[k][m], Bs[k][n], pad 4
    __shared__ float As[BK * PP];
    __shared__ float Bs[BK * PP];

    const int z = blockIdx.z;
    A += z * sA2; B += z * sB2; C += z * sC2;
    const int row0 = blockIdx.y * 128;
    const int col0 = blockIdx.x * 128;
    const int t = threadIdx.x;
    const int tx = t & 15, ty = t >> 4;

    float acc[8][8] = {};

    for (int k0 = 0; k0 < K; k0 += BK) {
        #pragma unroll
        for (int i = 0; i < 2; i++) {
            int f = t + i * 256;
            int r = f >> 2, c4 = (f & 3) << 2;
            float4 va = *reinterpret_cast<const float4*>(&A[(long)(row0 + r) * lda + k0 + c4]);
            As[(c4 + 0) * PP + r] = va.x; As[(c4 + 1) * PP + r] = va.y;
            As[(c4 + 2) * PP + r] = va.z; As[(c4 + 3) * PP + r] = va.w;
            float4 vb = *reinterpret_cast<const float4*>(&B[(long)(col0 + r) * ldb + k0 + c4]);
            Bs[(c4 + 0) * PP + r] = vb.x; Bs[(c4 + 1) * PP + r] = vb.y;
            Bs[(c4 + 2) * PP + r] = vb.z; Bs[(c4 + 3) * PP + r] = vb.w;
        }
        __syncthreads();

        #pragma unroll
        for (int kk = 0; kk < BK; kk++) {
            float4 a0 = *reinterpret_cast<const float4*>(&As[kk * PP + ty * 8]);
            float4 a1 = *reinterpret_cast<const float4*>(&As[kk * PP + ty * 8 + 4]);
            float4 b0 = *reinterpret_cast<const float4*>(&Bs[kk * PP + tx * 8]);
            float4 b1 = *reinterpret_cast<const float4*>(&Bs[kk * PP + tx * 8 + 4]);
            float a[8] = {a0.x, a0.y, a0.z, a0.w, a1.x, a1.y, a1.z, a1.w};
            float b[8] = {b0.x, b0.y, b0.z, b0.w, b1.x, b1.y, b1.z, b1.w};
            #pragma unroll
            for (int i = 0; i < 8; i++)
                #pragma unroll
                for (int j = 0; j < 8; j++)
                    acc[i][j] = fmaf(a[i], b[j], acc[i][j]);
        }
        __syncthreads();
    }

    #pragma unroll
    for (int i = 0; i < 8; i++) {
        long r = row0 + ty * 8 + i;
        #pragma unroll
        for (int j = 0; j < 8; j++)
            C[r * ldc + col0 + tx * 8 + j] = acc[i][j];
    }
}

// ---------------------------------------------------------------------------
// TF32 tensor-core NT GEMM, cp.async 3-stage pipeline.
// C = act(alpha * A @ B^T + bias).  A:(R,K) lda, B:(Cc,K) ldb.
// Tile 128x64x16, 256 threads (8 warps, 4x2), warp tile 32x32 (2x4 mmas).
// REQUIREMENT: R%128==0, Cc%64==0, K%16==0, all row starts 16B-aligned.
// fp32 operands fed raw to mma (hardware tf32 truncation).
// ---------------------------------------------------------------------------
template<int ACT>
__global__ void __launch_bounds__(256, 2) tgemm_nt(
    const float* __restrict__ A, const float* __restrict__ B,
    const float* __restrict__ bias, float* __restrict__ C,
    int R, int Cc, int K, int lda, int ldb, int ldc,
    long sA1, long sA2, long sB1, long sB2, long sC1, long sC2,
    int Z2, float alpha)
{
    constexpr int BM = 128, BN = 64, BK = 16, P = 20;   // pitch 16+4
    constexpr int STAGE = (BM + BN) * P;                // floats per stage
    __shared__ float sm[3 * STAGE];                     // 46080 B

    const int z  = blockIdx.z;
    const int z1 = z / Z2, z2 = z % Z2;
    A += z1 * sA1 + z2 * sA2;
    B += z1 * sB1 + z2 * sB2;
    C += z1 * sC1 + z2 * sC2;

    const int row0 = blockIdx.y * BM;
    const int col0 = blockIdx.x * BN;
    const int t    = threadIdx.x;
    const int lane = t & 31, wid = t >> 5;
    const int wm = wid & 3, wn = wid >> 2;

    const uint32_t smBase = (uint32_t)__cvta_generic_to_shared(sm);

    const int r8 = t >> 2;              // 0..63
    const int c4 = (t & 3) << 2;        // 0,4,8,12

    auto issue = [&](int kt, int s) {
        uint32_t sa = smBase + (uint32_t)(s * STAGE) * 4u;
        uint32_t sb = sa + (uint32_t)(BM * P) * 4u;
        int k0 = kt * BK;
        // A: 128 rows x 16 k = 512 float4, 2/thread
        #pragma unroll
        for (int i = 0; i < 2; i++) {
            int r = r8 + i * 64;
            cpa16(sa + (uint32_t)(r * P + c4) * 4u,
                  &A[(long)(row0 + r) * lda + k0 + c4]);
        }
        // B: 64 rows x 16 k = 256 float4, 1/thread
        cpa16(sb + (uint32_t)(r8 * P + c4) * 4u,
              &B[(long)(col0 + r8) * ldb + k0 + c4]);
        asm volatile("cp.async.commit_group;");
    };

    float accs[2][4][4];
    #pragma unroll
    for (int mt = 0; mt < 2; mt++)
        #pragma unroll
        for (int nt = 0; nt < 4; nt++)
            #pragma unroll
            for (int i = 0; i < 4; i++) accs[mt][nt][i] = 0.f;

    auto compute = [&](int s) {
        const uint32_t* asp = reinterpret_cast<const uint32_t*>(sm + s * STAGE);
        const uint32_t* bsp = asp + BM * P;
        #pragma unroll
        for (int ks = 0; ks < 2; ks++) {
            uint32_t af[2][4], bf[4][2];
            #pragma unroll
            for (int mt = 0; mt < 2; mt++) {
                int rb = wm * 32 + mt * 16 + (lane >> 2);
                int cb = ks * 8 + (lane & 3);
                af[mt][0] = asp[rb * P + cb];
                af[mt][1] = asp[(rb + 8) * P + cb];
                af[mt][2] = asp[rb * P + cb + 4];
                af[mt][3] = asp[(rb + 8) * P + cb + 4];
            }
            #pragma unroll
            for (int nt = 0; nt < 4; nt++) {
                int nb = wn * 32 + nt * 8 + (lane >> 2);
                int kb = ks * 8 + (lane & 3);
                bf[nt][0] = bsp[nb * P + kb];
                bf[nt][1] = bsp[nb * P + kb + 4];
            }
            #pragma unroll
            for (int mt = 0; mt < 2; mt++)
                #pragma unroll
                for (int nt = 0; nt < 4; nt++) {
                    float* c = accs[mt][nt];
                    asm volatile(
                        "mma.sync.aligned.m16n8k8.row.col.f32.tf32.tf32.f32 "
                        "{%0,%1,%2,%3}, {%4,%5,%6,%7}, {%8,%9}, {%0,%1,%2,%3};"
                        : "+f"(c[0]), "+f"(c[1]), "+f"(c[2]), "+f"(c[3])
                        : "r"(af[mt][0]), "r"(af[mt][1]), "r"(af[mt][2]), "r"(af[mt][3]),
                          "r"(bf[nt][0]), "r"(bf[nt][1]));
                }
        }
    };

    const int tiles = K / BK;
    if (0 < tiles) issue(0, 0);
    if (1 < tiles) issue(1, 1);

    for (int i = 0; i < tiles; i++) {
        if (i + 2 < tiles) issue(i + 2, (i + 2) % 3);
        if (i + 2 < tiles)      asm volatile("cp.async.wait_group 2;");
        else if (i + 1 < tiles) asm volatile("cp.async.wait_group 1;");
        else                    asm volatile("cp.async.wait_group 0;");
        __syncthreads();
        compute(i % 3);
        __syncthreads();
    }

    // epilogue (no bounds checks: dims divide tiles)
    #pragma unroll
    for (int mt = 0; mt < 2; mt++) {
        #pragma unroll
        for (int nt = 0; nt < 4; nt++) {
            int r = row0 + wm * 32 + mt * 16 + (lane >> 2);
            int c = col0 + wn * 32 + nt * 8 + ((lane & 3) << 1);
            float* acc = accs[mt][nt];
            #pragma unroll
            for (int e = 0; e < 4; e++) {
                int rr = r + (e >> 1) * 8;
                int cc = c + (e & 1);
                float v = acc[e] * alpha;
                if (bias) v += bias[cc];
                if (ACT == 1) v = 0.5f * v * (1.0f + erff(v * 0.70710678118654752f));
                C[(long)rr * ldc + cc] = v;
            }
        }
    }
}

// ---------------------------------------------------------------------------
// TF32 NN GEMM (register-staged, for PV only): C = A @ B, small.
// Tile 128x32x32, 256 threads, warps 8x1.
// ---------------------------------------------------------------------------
__global__ void tgemm_nn_pv(
    const float* __restrict__ A, const float* __restrict__ B,
    float* __restrict__ C,
    int R, int Cc, int K, int lda, int ldb, int ldc,
    long sA1, long sA2, long sB1, long sB2, long sC1, long sC2,
    int Z2)
{
    constexpr int BM = 128, BN = 32, BK = 32, LDS = BK + 4;
    __shared__ float As[BM * LDS];
    __shared__ float Bs[BN * LDS];

    const int z  = blockIdx.z;
    const int z1 = z / Z2, z2 = z % Z2;
    A += z1 * sA1 + z2 * sA2;
    B += z1 * sB1 + z2 * sB2;
    C += z1 * sC1 + z2 * sC2;

    const int row0 = blockIdx.y * BM;
    const int t    = threadIdx.x;
    const int lane = t & 31, wid = t >> 5;

    float4 aR[4];
    float  bRn[4];
    const int arow = t >> 3;
    const int acol = (t & 7) << 2;

    auto loadA = [&](int k0) {
        #pragma unroll
        for (int i = 0; i < 4; i++) {
            int r = row0 + arow + i * 32;
            aR[i] = *reinterpret_cast<const float4*>(&A[(long)r * lda + k0 + acol]);
        }
    };
    auto loadB = [&](int k0) {
        #pragma unroll
        for (int i = 0; i < 4; i++) {
            int e = t + i * 256;
            int n = e & 31;
            int k = e >> 5;
            bRn[i] = B[(long)(k0 + k) * ldb + n];
        }
    };
    auto storeStage = [&]() {
        #pragma unroll
        for (int i = 0; i < 4; i++) {
            float4 v = aR[i];
            v.x = ftf32(v.x); v.y = ftf32(v.y); v.z = ftf32(v.z); v.w = ftf32(v.w);
            *reinterpret_cast<float4*>(&As[(arow + i * 32) * LDS + acol]) = v;
        }
        #pragma unroll
        for (int i = 0; i < 4; i++) {
            int e = t + i * 256;
            int n = e & 31;
            int k = e >> 5;
            Bs[n * LDS + k] = ftf32(bRn[i]);
        }
    };

    float accs[4][4];
    #pragma unroll
    for (int nt = 0; nt < 4; nt++)
        #pragma unroll
        for (int i = 0; i < 4; i++) accs[nt][i] = 0.f;

    const uint32_t* asp = reinterpret_cast<const uint32_t*>(As);
    const uint32_t* bsp = reinterpret_cast<const uint32_t*>(Bs);

    auto compute = [&]() {
        #pragma unroll
        for (int ks = 0; ks < 4; ks++) {
            uint32_t af[4], bf[4][2];
            int rb = wid * 16 + (lane >> 2);
            int cb = ks * 8 + (lane & 3);
            af[0] = asp[rb * LDS + cb];
            af[1] = asp[(rb + 8) * LDS + cb];
            af[2] = asp[rb * LDS + cb + 4];
            af[3] = asp[(rb + 8) * LDS + cb + 4];
            #pragma unroll
            for (int nt = 0; nt < 4; nt++) {
                int nb = nt * 8 + (lane >> 2);
                int kb = ks * 8 + (lane & 3);
                bf[nt][0] = bsp[nb * LDS + kb];
                bf[nt][1] = bsp[nb * LDS + kb + 4];
            }
            #pragma unroll
            for (int nt = 0; nt < 4; nt++) {
                float* c = accs[nt];
                asm volatile(
                    "mma.sync.aligned.m16n8k8.row.col.f32.tf32.tf32.f32 "
                    "{%0,%1,%2,%3}, {%4,%5,%6,%7}, {%8,%9}, {%0,%1,%2,%3};"
                    : "+f"(c[0]), "+f"(c[1]), "+f"(c[2]), "+f"(c[3])
                    : "r"(af[0]), "r"(af[1]), "r"(af[2]), "r"(af[3]),
                      "r"(bf[nt][0]), "r"(bf[nt][1]));
            }
        }
    };

    loadA(0); loadB(0);
    int k0 = 0;
    for (;;) {
        storeStage();
        __syncthreads();
        k0 += BK;
        bool more = (k0 < K);
        if (more) { loadA(k0); loadB(k0); }
        compute();
        if (!more) break;
        __syncthreads();
    }

    #pragma unroll
    for (int nt = 0; nt < 4; nt++) {
        int r = row0 + wid * 16 + (lane >> 2);
        int c = nt * 8 + ((lane & 3) << 1);
        float* acc = accs[nt];
        #pragma unroll
        for (int e = 0; e < 4; e++) {
            int rr = r + (e >> 1) * 8;
            int cc = c + (e & 1);
            C[(long)rr * ldc + cc] = acc[e];
        }
    }
}

// ---------------------------------------------------------------------------
// Inverse L2 norm of each memory row (m,b)
// ---------------------------------------------------------------------------
__global__ void inv_norm_kernel(const float* __restrict__ mem, float* __restrict__ mnorm)
{
    int r    = blockIdx.x * 8 + (threadIdx.x >> 5);
    int lane = threadIdx.x & 31;
    const float* p = mem + (long)r * DIM;
    float s = 0.f;
    #pragma unroll
    for (int j = lane; j < DIM; j += 32) { float x = p[j]; s = fmaf(x, x, s); }
    #pragma unroll
    for (int o = 16; o; o >>= 1) s += __shfl_xor_sync(0xffffffffu, s, o);
    if (lane == 0) mnorm[r] = 1.0f / sqrtf(s);
}

// ---------------------------------------------------------------------------
// Top-32 of sim[b,n,:] * mnorm. Iterative argmax, lowest-index tie-break.
// ---------------------------------------------------------------------------
__global__ void topk_kernel(const float* __restrict__ sim,
                            const float* __restrict__ mnorm,
                            int* __restrict__ rns)
{
    int n = blockIdx.x, b = blockIdx.y;
    const float* row = sim + ((long)b * NP + n) * MNP;
    int t = threadIdx.x;
    __shared__ float sv[MNP];
    __shared__ float swv[8];
    __shared__ int   swi[8];
    __shared__ int   sbest;

    #pragma unroll
    for (int j = 0; j < MNP / 256; j++) {
        int m = t + j * 256;
        sv[m] = row[m] * mnorm[m * BSZ + b];
    }
    __syncthreads();

    int lane = t & 31, w = t >> 5;
    for (int it = 0; it < TOPK; it++) {
        float bv = -INFINITY; int bi = 0x7fffffff;
        #pragma unroll
        for (int j = 0; j < MNP / 256; j++) {
            int m = t + j * 256;
            float v = sv[m];
            if (v > bv || (v == bv && m < bi)) { bv = v; bi = m; }
        }
        #pragma unroll
        for (int o = 16; o; o >>= 1) {
            float ov = __shfl_xor_sync(0xffffffffu, bv, o);
            int   oi = __shfl_xor_sync(0xffffffffu, bi, o);
            if (ov > bv || (ov == bv && oi < bi)) { bv = ov; bi = oi; }
        }
        if (lane == 0) { swv[w] = bv; swi[w] = bi; }
        __syncthreads();
        if (t == 0) {
            float Bv = swv[0]; int Bi = swi[0];
            #pragma unroll
            for (int k = 1; k < 8; k++)
                if (swv[k] > Bv || (swv[k] == Bv && swi[k] < Bi)) { Bv = swv[k]; Bi = swi[k]; }
            sbest = Bi;
            rns[((long)b * NP + n) * TOPK + it] = Bi;
        }
        __syncthreads();
        if (t == 0) sv[sbest] = -INFINITY;
        __syncthreads();
    }
}

// ---------------------------------------------------------------------------
// Sparse cross-attention: one warp per head, softmax over TOPK keys.
// ---------------------------------------------------------------------------
__global__ void cross_attn_kernel(const float* __restrict__ Q,
                                  const float* __restrict__ Kb,
                                  const float* __restrict__ Vb,
                                  const int*   __restrict__ rns,
                                  float* __restrict__ cross)
{
    int n = blockIdx.x, b = blockIdx.y;
    int t = threadIdx.x, h = t >> 5, lane = t & 31;
    __shared__ int idx[TOPK];
    if (t < TOPK) idx[t] = rns[((long)b * NP + n) * TOPK + t];
    __syncthreads();

    long qoff = ((long)n * BSZ + b) * DIM + h * HD;
    float q = Q[qoff + lane];

    float myscore = -INFINITY;
    #pragma unroll
    for (int j = 0; j < TOPK; j++) {
        float prod = q * Kb[((long)idx[j] * BSZ + b) * DIM + h * HD + lane];
        #pragma unroll
        for (int o = 16; o; o >>= 1) prod += __shfl_xor_sync(0xffffffffu, prod, o);
        if (lane == j) myscore = prod * ATT_SCALE;
    }
    float mx = myscore;
    #pragma unroll
    for (int o = 16; o; o >>= 1) mx = fmaxf(mx, __shfl_xor_sync(0xffffffffu, mx, o));
    float e = expf(myscore - mx);
    float s = e;
    #pragma unroll
    for (int o = 16; o; o >>= 1) s += __shfl_xor_sync(0xffffffffu, s, o);
    float p = e / s;

    float acc = 0.f;
    #pragma unroll
    for (int j = 0; j < TOPK; j++) {
        float pj = __shfl_sync(0xffffffffu, p, j);
        acc = fmaf(pj, Vb[((long)idx[j] * BSZ + b) * DIM + h * HD + lane], acc);
    }
    cross[qoff + lane] = acc;
}

// ---------------------------------------------------------------------------
// out = LayerNorm(a + c) * w + beta
// ---------------------------------------------------------------------------
__global__ void add_ln_kernel(const float* __restrict__ a, const float* __restrict__ c,
                              const float* __restrict__ w, const float* __restrict__ beta,
                              float* __restrict__ out)
{
    long r = blockIdx.x;
    int  t = threadIdx.x;
    float x = a[r * DIM + t] + c[r * DIM + t];
    __shared__ float red[8];

    float s = x;
    #pragma unroll
    for (int o = 16; o; o >>= 1) s += __shfl_xor_sync(0xffffffffu, s, o);
    if ((t & 31) == 0) red[t >> 5] = s;
    __syncthreads();
    float tot = 0.f;
    #pragma unroll
    for (int k = 0; k < 8; k++) tot += red[k];
    float mu = tot * (1.0f / DIM);
    __syncthreads();

    float d  = x - mu;
    float s2 = d * d;
    #pragma unroll
    for (int o = 16; o; o >>= 1) s2 += __shfl_xor_sync(0xffffffffu, s2, o);
    if ((t & 31) == 0) red[t >> 5] = s2;
    __syncthreads();
    float tot2 = 0.f;
    #pragma unroll
    for (int k = 0; k < 8; k++) tot2 += red[k];
    float var = tot2 * (1.0f / DIM);

    out[r * DIM + t] = d * rsqrtf(var + LN_EPS) * w[t] + beta[t];
}

// ---------------------------------------------------------------------------
// In-place softmax over rows of length 512
// ---------------------------------------------------------------------------
__global__ void softmax512_kernel(float* __restrict__ sc)
{
    long r = blockIdx.x;
    float* row = sc + r * 512;
    int t = threadIdx.x;
    float a = row[t], b = row[t + 256];
    __shared__ float red[8];

    float m = fmaxf(a, b);
    #pragma unroll
    for (int o = 16; o; o >>= 1) m = fmaxf(m, __shfl_xor_sync(0xffffffffu, m, o));
    if ((t & 31) == 0) red[t >> 5] = m;
    __syncthreads();
    float M = -INFINITY;
    #pragma unroll
    for (int k = 0; k < 8; k++) M = fmaxf(M, red[k]);
    __syncthreads();

    float ea = expf(a - M), eb = expf(b - M);
    float s = ea + eb;
    #pragma unroll
    for (int o = 16; o; o >>= 1) s += __shfl_xor_sync(0xffffffffu, s, o);
    if ((t & 31) == 0) red[t >> 5] = s;
    __syncthreads();
    float tot = 0.f;
    #pragma unroll
    for (int k = 0; k < 8; k++) tot += red[k];
    float inv = 1.0f / tot;
    row[t] = ea * inv;
    row[t + 256] = eb * inv;
}

// ---------------------------------------------------------------------------
// Launch
// ---------------------------------------------------------------------------
extern "C" void kernel_launch(void* const* d_in, const int* in_sizes, int n_in,
                              void* d_out, int out_size)
{
    const float* tgt      = (const float*)d_in[0];
    const float* memory   = (const float*)d_in[1];
    const float* qpos     = (const float*)d_in[2];
    const float* kpos     = (const float*)d_in[3];
    const float* cw1      = (const float*)d_in[4];
    const float* cb1      = (const float*)d_in[5];
    const float* cw2      = (const float*)d_in[6];
    const float* cb2      = (const float*)d_in[7];
    const float* cw3      = (const float*)d_in[8];
    const float* cb3      = (const float*)d_in[9];
    const float* sa_in_w  = (const float*)d_in[10];
    const float* sa_in_b  = (const float*)d_in[11];
    const float* sa_out_w = (const float*)d_in[12];
    const float* sa_out_b = (const float*)d_in[13];
    const float* ln1_w    = (const float*)d_in[14];
    const float* ln1_b    = (const float*)d_in[15];
    const float* ln2_w    = (const float*)d_in[16];
    const float* ln2_b    = (const float*)d_in[17];
    const float* ln3_w    = (const float*)d_in[18];
    const float* ln3_b    = (const float*)d_in[19];
    const float* ff1_w    = (const float*)d_in[20];
    const float* ff1_b    = (const float*)d_in[21];
    const float* ff2_w    = (const float*)d_in[22];
    const float* ff2_b    = (const float*)d_in[23];
    float* out = (float*)d_out;

    void *p;
    cudaGetSymbolAddress(&p, g_sim);   float* sim   = (float*)p;
    cudaGetSymbolAddress(&p, g_mnorm); float* mnorm = (float*)p;
    cudaGetSymbolAddress(&p, g_rns);   int*   rns   = (int*)p;
    cudaGetSymbolAddress(&p, g_K);     float* Kb    = (float*)p;
    cudaGetSymbolAddress(&p, g_V);     float* Vb    = (float*)p;
    cudaGetSymbolAddress(&p, g_Q);     float* Qb    = (float*)p;
    cudaGetSymbolAddress(&p, g_cross); float* cross = (float*)p;
    cudaGetSymbolAddress(&p, g_t1);    float* t1    = (float*)p;
    cudaGetSymbolAddress(&p, g_QK2);   float* QK2   = (float*)p;
    cudaGetSymbolAddress(&p, g_V2);    float* V2    = (float*)p;
    cudaGetSymbolAddress(&p, g_sc2);   float* sc2   = (float*)p;
    cudaGetSymbolAddress(&p, g_sa);    float* sa    = (float*)p;
    cudaGetSymbolAddress(&p, g_sa2);   float* sa2   = (float*)p;
    cudaGetSymbolAddress(&p, g_t2);    float* t2    = (float*)p;
    cudaGetSymbolAddress(&p, g_ffh);   float* ffh   = (float*)p;
    cudaGetSymbolAddress(&p, g_ffo);   float* ffo   = (float*)p;
    cudaGetSymbolAddress(&p, g_madd);  float* madd  = (float*)p;
    cudaGetSymbolAddress(&p, g_qadd);  float* qadd  = (float*)p;

    const long BD = (long)BSZ * DIM;   // 2048

    // 1) inverse norms of memory rows
    inv_norm_kernel<<<MNP * BSZ / 8, 256>>>(memory, mnorm);

    // 2) sim[b,n,m] = tgt . memory — EXACT fp32 (feeds top-k)
    sim_sgemm2<<<dim3(MNP / 128, NP / 128, BSZ), 256>>>(
        tgt, memory, sim,
        DIM, (int)BD, (int)BD, MNP,
        DIM, DIM, (long)NP * MNP);

    // 3) top-32 indices
    topk_kernel<<<dim3(NP, BSZ), 256>>>(sim, mnorm, rns);

    // pre-adds for fused position inputs
    vecadd_kernel<<<(MNP * BSZ * DIM / 4 + 255) / 256, 256>>>(memory, kpos, madd, MNP * BSZ * DIM / 4);
    vecadd_kernel<<<(NP * BSZ * DIM / 4 + 255) / 256, 256>>>(tgt, qpos, qadd, NP * BSZ * DIM / 4);

    // 4) cross projections (TF32 cp.async pipeline)
    tgemm_nt<0><<<dim3(DIM / 64, MNP * BSZ / 128, 1), 256>>>(
        madd, cw2, cb2, Kb,
        MNP * BSZ, DIM, DIM, DIM, DIM, DIM, 0, 0, 0, 0, 0, 0, 1, 1.0f);
    tgemm_nt<0><<<dim3(DIM / 64, MNP * BSZ / 128, 1), 256>>>(
        memory, cw3, cb3, Vb,
        MNP * BSZ, DIM, DIM, DIM, DIM, DIM, 0, 0, 0, 0, 0, 0, 1, 1.0f);
    tgemm_nt<0><<<dim3(DIM / 64, NP * BSZ / 128, 1), 256>>>(
        qadd, cw1, cb1, Qb,
        NP * BSZ, DIM, DIM, DIM, DIM, DIM, 0, 0, 0, 0, 0, 0, 1, 1.0f);

    // 5) sparse cross-attention, 6) t1 = LN(tgt + cross)
    cross_attn_kernel<<<dim3(NP, BSZ), 256>>>(Qb, Kb, Vb, rns, cross);
    add_ln_kernel<<<NP * BSZ, 256>>>(tgt, cross, ln1_w, ln1_b, t1);

    // 7) self-attn projections: Q2|K2 fused (Cc=512), V2 separate
    vecadd_kernel<<<(NP * BSZ * DIM / 4 + 255) / 256, 256>>>(t1, qpos, qadd, NP * BSZ * DIM / 4);
    tgemm_nt<0><<<dim3(2 * DIM / 64, NP * BSZ / 128, 1), 256>>>(
        qadd, sa_in_w, sa_in_b, QK2,
        NP * BSZ, 2 * DIM, DIM, DIM, DIM, 2 * DIM, 0, 0, 0, 0, 0, 0, 1, 1.0f);
    tgemm_nt<0><<<dim3(DIM / 64, NP * BSZ / 128, 1), 256>>>(
        t1, sa_in_w + 2 * DIM * DIM, sa_in_b + 2 * DIM, V2,
        NP * BSZ, DIM, DIM, DIM, DIM, DIM, 0, 0, 0, 0, 0, 0, 1, 1.0f);

    // 8) scores[b,h,n,m] = scale * Q2 . K2
    tgemm_nt<0><<<dim3(NP / 64, NP / 128, BSZ * NH), 256>>>(
        QK2, QK2 + DIM, nullptr, sc2,
        NP, NP, HD, (int)(BSZ * 2 * DIM), (int)(BSZ * 2 * DIM), NP,
        2 * DIM, HD, 2 * DIM, HD, (long)NH * NP * NP, (long)NP * NP, NH, ATT_SCALE);

    // 9) softmax over keys
    softmax512_kernel<<<BSZ * NH * NP, 256>>>(sc2);

    // 10) sa = P @ V2 (NN), written into (n,b,dim) layout
    tgemm_nn_pv<<<dim3(1, NP / 128, BSZ * NH), 256>>>(
        sc2, V2, sa,
        NP, HD, NP, NP, (int)BD, (int)BD,
        (long)NH * NP * NP, (long)NP * NP, DIM, HD, DIM, HD, NH);

    // 11) out projection, 12) t2 = LN(t1 + sa2)
    tgemm_nt<0><<<dim3(DIM / 64, NP * BSZ / 128, 1), 256>>>(
        sa, sa_out_w, sa_out_b, sa2,
        NP * BSZ, DIM, DIM, DIM, DIM, DIM, 0, 0, 0, 0, 0, 0, 1, 1.0f);
    add_ln_kernel<<<NP * BSZ, 256>>>(t1, sa2, ln2_w, ln2_b, t2);

    // 13) FFN + final LN
    tgemm_nt<1><<<dim3(FF / 64, NP * BSZ / 128, 1), 256>>>(
        t2, ff1_w, ff1_b, ffh,
        NP * BSZ, FF, DIM, DIM, DIM, FF, 0, 0, 0, 0, 0, 0, 1, 1.0f);
    tgemm_nt<0><<<dim3(DIM / 64, NP * BSZ / 128, 1), 256>>>(
        ffh, ff2_w, ff2_b, ffo,
        NP * BSZ, DIM, FF, FF, FF, DIM, 0, 0, 0, 0, 0, 0, 1, 1.0f);
    add_ln_kernel<<<NP * BSZ, 256>>>(t2, ffo, ln3_w, ln3_b, out);
}

// round 5
// speedup vs baseline: 2.0977x; 1.2787x over previous
#include <cuda_runtime.h>
#include <cuda_bf16.h>
#include <math.h>
#include <stdint.h>

#define NP   512
#define MNP  4096
#define BSZ  8
#define DIM  256
#define NH   8
#define TOPK 32
#define FF   2048
#define HD   32
#define LN_EPS 1e-5f
#define ATT_SCALE 0.17677669529663687f   /* 1/sqrt(32) */

// ---------------------------------------------------------------------------
// Scratch
// ---------------------------------------------------------------------------
__device__ float g_sim   [BSZ * NP * MNP];
__device__ float g_mnorm [MNP * BSZ];
__device__ int   g_rns   [BSZ * NP * TOPK];
__device__ float g_K     [MNP * BSZ * DIM];
__device__ float g_V     [MNP * BSZ * DIM];
__device__ float g_Q     [NP * BSZ * DIM];
__device__ float g_t1    [NP * BSZ * DIM];
__device__ float g_QK2   [NP * BSZ * 2 * DIM];
__device__ float g_V2    [NP * BSZ * DIM];
__device__ float g_sa    [NP * BSZ * DIM];
__device__ float g_sa2   [NP * BSZ * DIM];
__device__ float g_t2    [NP * BSZ * DIM];
__device__ float g_ffh   [NP * BSZ * FF];
__device__ float g_ffo   [2 * NP * BSZ * DIM];   // split-K partials
__device__ float g_madd  [MNP * BSZ * DIM];
__device__ float g_qadd  [NP * BSZ * DIM];

__device__ __forceinline__ float ftf32(float x) {
    uint32_t u;
    asm("cvt.rna.tf32.f32 %0, %1;" : "=r"(u) : "f"(x));
    return __uint_as_float(u);
}
__device__ __forceinline__ void cpa16(uint32_t dst, const float* src) {
    asm volatile("cp.async.cg.shared.global [%0], [%1], 16;" :: "r"(dst), "l"(src));
}

// ---------------------------------------------------------------------------
// Elementwise o = a + b
// ---------------------------------------------------------------------------
__global__ void vecadd_kernel(const float* __restrict__ a, const float* __restrict__ b,
                              float* __restrict__ o, int n4)
{
    int i = blockIdx.x * blockDim.x + threadIdx.x;
    if (i < n4) {
        float4 x = ((const float4*)a)[i];
        float4 y = ((const float4*)b)[i];
        x.x += y.x; x.y += y.y; x.z += y.z; x.w += y.w;
        ((float4*)o)[i] = x;
    }
}

// ---------------------------------------------------------------------------
// EXACT fp32 FFMA SGEMM (NT) for the sim GEMM feeding top-k.
// ---------------------------------------------------------------------------
__global__ void __launch_bounds__(256) sim_sgemm2(
    const float* __restrict__ A, const float* __restrict__ B, float* __restrict__ C,
    int K, int lda, int ldb, int ldc, long sA2, long sB2, long sC2)
{
    constexpr int BK = 16, PP = 132;
    __shared__ float As[BK * PP];
    __shared__ float Bs[BK * PP];

    const int z = blockIdx.z;
    A += z * sA2; B += z * sB2; C += z * sC2;
    const int row0 = blockIdx.y * 128;
    const int col0 = blockIdx.x * 128;
    const int t = threadIdx.x;
    const int tx = t & 15, ty = t >> 4;

    float acc[8][8] = {};

    for (int k0 = 0; k0 < K; k0 += BK) {
        #pragma unroll
        for (int i = 0; i < 2; i++) {
            int f = t + i * 256;
            int r = f >> 2, c4 = (f & 3) << 2;
            float4 va = *reinterpret_cast<const float4*>(&A[(long)(row0 + r) * lda + k0 + c4]);
            As[(c4 + 0) * PP + r] = va.x; As[(c4 + 1) * PP + r] = va.y;
            As[(c4 + 2) * PP + r] = va.z; As[(c4 + 3) * PP + r] = va.w;
            float4 vb = *reinterpret_cast<const float4*>(&B[(long)(col0 + r) * ldb + k0 + c4]);
            Bs[(c4 + 0) * PP + r] = vb.x; Bs[(c4 + 1) * PP + r] = vb.y;
            Bs[(c4 + 2) * PP + r] = vb.z; Bs[(c4 + 3) * PP + r] = vb.w;
        }
        __syncthreads();

        #pragma unroll
        for (int kk = 0; kk < BK; kk++) {
            float4 a0 = *reinterpret_cast<const float4*>(&As[kk * PP + ty * 8]);
            float4 a1 = *reinterpret_cast<const float4*>(&As[kk * PP + ty * 8 + 4]);
            float4 b0 = *reinterpret_cast<const float4*>(&Bs[kk * PP + tx * 8]);
            float4 b1 = *reinterpret_cast<const float4*>(&Bs[kk * PP + tx * 8 + 4]);
            float a[8] = {a0.x, a0.y, a0.z, a0.w, a1.x, a1.y, a1.z, a1.w};
            float b[8] = {b0.x, b0.y, b0.z, b0.w, b1.x, b1.y, b1.z, b1.w};
            #pragma unroll
            for (int i = 0; i < 8; i++)
                #pragma unroll
                for (int j = 0; j < 8; j++)
                    acc[i][j] = fmaf(a[i], b[j], acc[i][j]);
        }
        __syncthreads();
    }

    #pragma unroll
    for (int i = 0; i < 8; i++) {
        long r = row0 + ty * 8 + i;
        #pragma unroll
        for (int j = 0; j < 8; j++)
            C[r * ldc + col0 + tx * 8 + j] = acc[i][j];
    }
}

// ---------------------------------------------------------------------------
// TF32 tensor-core NT GEMM, cp.async 3-stage pipeline (same as R4).
// ---------------------------------------------------------------------------
template<int ACT>
__global__ void __launch_bounds__(256, 2) tgemm_nt(
    const float* __restrict__ A, const float* __restrict__ B,
    const float* __restrict__ bias, float* __restrict__ C,
    int R, int Cc, int K, int lda, int ldb, int ldc,
    long sA1, long sA2, long sB1, long sB2, long sC1, long sC2,
    int Z2, float alpha)
{
    constexpr int BM = 128, BN = 64, BK = 16, P = 20;
    constexpr int STAGE = (BM + BN) * P;
    __shared__ float sm[3 * STAGE];

    const int z  = blockIdx.z;
    const int z1 = z / Z2, z2 = z % Z2;
    A += z1 * sA1 + z2 * sA2;
    B += z1 * sB1 + z2 * sB2;
    C += z1 * sC1 + z2 * sC2;

    const int row0 = blockIdx.y * BM;
    const int col0 = blockIdx.x * BN;
    const int t    = threadIdx.x;
    const int lane = t & 31, wid = t >> 5;
    const int wm = wid & 3, wn = wid >> 2;

    const uint32_t smBase = (uint32_t)__cvta_generic_to_shared(sm);
    const int r8 = t >> 2;
    const int c4 = (t & 3) << 2;

    auto issue = [&](int kt, int s) {
        uint32_t sa_ = smBase + (uint32_t)(s * STAGE) * 4u;
        uint32_t sb_ = sa_ + (uint32_t)(BM * P) * 4u;
        int k0 = kt * BK;
        #pragma unroll
        for (int i = 0; i < 2; i++) {
            int r = r8 + i * 64;
            cpa16(sa_ + (uint32_t)(r * P + c4) * 4u, &A[(long)(row0 + r) * lda + k0 + c4]);
        }
        cpa16(sb_ + (uint32_t)(r8 * P + c4) * 4u, &B[(long)(col0 + r8) * ldb + k0 + c4]);
        asm volatile("cp.async.commit_group;");
    };

    float accs[2][4][4];
    #pragma unroll
    for (int mt = 0; mt < 2; mt++)
        #pragma unroll
        for (int nt = 0; nt < 4; nt++)
            #pragma unroll
            for (int i = 0; i < 4; i++) accs[mt][nt][i] = 0.f;

    auto compute = [&](int s) {
        const uint32_t* asp = reinterpret_cast<const uint32_t*>(sm + s * STAGE);
        const uint32_t* bsp = asp + BM * P;
        #pragma unroll
        for (int ks = 0; ks < 2; ks++) {
            uint32_t af[2][4], bf[4][2];
            #pragma unroll
            for (int mt = 0; mt < 2; mt++) {
                int rb = wm * 32 + mt * 16 + (lane >> 2);
                int cb = ks * 8 + (lane & 3);
                af[mt][0] = asp[rb * P + cb];
                af[mt][1] = asp[(rb + 8) * P + cb];
                af[mt][2] = asp[rb * P + cb + 4];
                af[mt][3] = asp[(rb + 8) * P + cb + 4];
            }
            #pragma unroll
            for (int nt = 0; nt < 4; nt++) {
                int nb = wn * 32 + nt * 8 + (lane >> 2);
                int kb = ks * 8 + (lane & 3);
                bf[nt][0] = bsp[nb * P + kb];
                bf[nt][1] = bsp[nb * P + kb + 4];
            }
            #pragma unroll
            for (int mt = 0; mt < 2; mt++)
                #pragma unroll
                for (int nt = 0; nt < 4; nt++) {
                    float* c = accs[mt][nt];
                    asm volatile(
                        "mma.sync.aligned.m16n8k8.row.col.f32.tf32.tf32.f32 "
                        "{%0,%1,%2,%3}, {%4,%5,%6,%7}, {%8,%9}, {%0,%1,%2,%3};"
                        : "+f"(c[0]), "+f"(c[1]), "+f"(c[2]), "+f"(c[3])
                        : "r"(af[mt][0]), "r"(af[mt][1]), "r"(af[mt][2]), "r"(af[mt][3]),
                          "r"(bf[nt][0]), "r"(bf[nt][1]));
                }
        }
    };

    const int tiles = K / BK;
    if (0 < tiles) issue(0, 0);
    if (1 < tiles) issue(1, 1);

    for (int i = 0; i < tiles; i++) {
        if (i + 2 < tiles) issue(i + 2, (i + 2) % 3);
        if (i + 2 < tiles)      asm volatile("cp.async.wait_group 2;");
        else if (i + 1 < tiles) asm volatile("cp.async.wait_group 1;");
        else                    asm volatile("cp.async.wait_group 0;");
        __syncthreads();
        compute(i % 3);
        __syncthreads();
    }

    #pragma unroll
    for (int mt = 0; mt < 2; mt++) {
        #pragma unroll
        for (int nt = 0; nt < 4; nt++) {
            int r = row0 + wm * 32 + mt * 16 + (lane >> 2);
            int c = col0 + wn * 32 + nt * 8 + ((lane & 3) << 1);
            float* acc = accs[mt][nt];
            #pragma unroll
            for (int e = 0; e < 4; e++) {
                int rr = r + (e >> 1) * 8;
                int cc = c + (e & 1);
                float v = acc[e] * alpha;
                if (bias) v += bias[cc];
                if (ACT == 1) v = 0.5f * v * (1.0f + erff(v * 0.70710678118654752f));
                C[(long)rr * ldc + cc] = v;
            }
        }
    }
}

// ---------------------------------------------------------------------------
// Fused flash self-attention: per (qtile, b*NH+h) block.
// S = (Q @ K^T) * scale ; online softmax ; O = P @ V. Tensor-core tf32.
// BM=128 queries, CH=32 key chunk, 8 warps (16 q-rows each).
// ---------------------------------------------------------------------------
__global__ void __launch_bounds__(256) flash_sa_kernel(
    const float* __restrict__ QK2, const float* __restrict__ V2,
    float* __restrict__ sa)
{
    constexpr int QP = 36, KP = 36, VP = 36, PP = 36, CH = 32, NCH = NP / CH;
    __shared__ float Qs[128 * QP];
    __shared__ float Ks[CH * KP];
    __shared__ float Vs[HD * VP];     // transposed: [d][key]
    __shared__ float Ps[128 * PP];

    const int q0 = blockIdx.x * 128;
    const int bh = blockIdx.y;
    const int b  = bh >> 3, h = bh & 7;
    const int t  = threadIdx.x, lane = t & 31, wm = t >> 5;

    // load Q tile (raw fp32; mma truncates to tf32 like the R4 scores GEMM)
    {
        int r = t >> 1, c0 = (t & 1) * 16;
        const float* src = QK2 + ((long)(q0 + r) * BSZ + b) * 512 + h * HD + c0;
        #pragma unroll
        for (int i = 0; i < 4; i++)
            *reinterpret_cast<float4*>(&Qs[r * QP + c0 + i * 4]) =
                *reinterpret_cast<const float4*>(src + i * 4);
    }

    float m0 = -INFINITY, m1 = -INFINITY, l0 = 0.f, l1 = 0.f;
    float o[4][4] = {};
    const int rA  = wm * 16 + (lane >> 2);
    const int cq  = lane & 3;

    for (int kt = 0; kt < NCH; kt++) {
        // load K chunk [CH x 32] and V chunk transposed [32 x CH]
        if (t < 64) {
            int r = t >> 1, c0 = (t & 1) * 16;
            const float* src = QK2 + ((long)(kt * CH + r) * BSZ + b) * 512 + DIM + h * HD + c0;
            #pragma unroll
            for (int i = 0; i < 4; i++)
                *reinterpret_cast<float4*>(&Ks[r * KP + c0 + i * 4]) =
                    *reinterpret_cast<const float4*>(src + i * 4);
        } else if (t < 128) {
            int tt = t - 64;
            int key = tt >> 1, c0 = (tt & 1) * 16;
            const float* src = V2 + ((long)(kt * CH + key) * BSZ + b) * DIM + h * HD + c0;
            #pragma unroll
            for (int i = 0; i < 4; i++) {
                float4 v = *reinterpret_cast<const float4*>(src + i * 4);
                Vs[(c0 + i * 4 + 0) * VP + key] = ftf32(v.x);
                Vs[(c0 + i * 4 + 1) * VP + key] = ftf32(v.y);
                Vs[(c0 + i * 4 + 2) * VP + key] = ftf32(v.z);
                Vs[(c0 + i * 4 + 3) * VP + key] = ftf32(v.w);
            }
        }
        __syncthreads();

        // S = Q @ K^T  (warp: 16 rows x 32 keys)
        float s[4][4];
        #pragma unroll
        for (int nt = 0; nt < 4; nt++)
            #pragma unroll
            for (int e = 0; e < 4; e++) s[nt][e] = 0.f;

        const uint32_t* qsp = reinterpret_cast<const uint32_t*>(Qs);
        const uint32_t* ksp = reinterpret_cast<const uint32_t*>(Ks);
        #pragma unroll
        for (int ks = 0; ks < 4; ks++) {
            int cb = ks * 8 + cq;
            uint32_t a0 = qsp[rA * QP + cb];
            uint32_t a1 = qsp[(rA + 8) * QP + cb];
            uint32_t a2 = qsp[rA * QP + cb + 4];
            uint32_t a3 = qsp[(rA + 8) * QP + cb + 4];
            #pragma unroll
            for (int nt = 0; nt < 4; nt++) {
                int nb = nt * 8 + (lane >> 2);
                uint32_t b0 = ksp[nb * KP + cb];
                uint32_t b1 = ksp[nb * KP + cb + 4];
                float* c = s[nt];
                asm volatile(
                    "mma.sync.aligned.m16n8k8.row.col.f32.tf32.tf32.f32 "
                    "{%0,%1,%2,%3}, {%4,%5,%6,%7}, {%8,%9}, {%0,%1,%2,%3};"
                    : "+f"(c[0]), "+f"(c[1]), "+f"(c[2]), "+f"(c[3])
                    : "r"(a0), "r"(a1), "r"(a2), "r"(a3), "r"(b0), "r"(b1));
            }
        }

        // scale and per-row online softmax (rows rA and rA+8)
        float mxA = -INFINITY, mxB = -INFINITY;
        #pragma unroll
        for (int nt = 0; nt < 4; nt++) {
            #pragma unroll
            for (int e = 0; e < 4; e++) s[nt][e] *= ATT_SCALE;
            mxA = fmaxf(mxA, fmaxf(s[nt][0], s[nt][1]));
            mxB = fmaxf(mxB, fmaxf(s[nt][2], s[nt][3]));
        }
        #pragma unroll
        for (int off = 1; off <= 2; off <<= 1) {
            mxA = fmaxf(mxA, __shfl_xor_sync(0xffffffffu, mxA, off));
            mxB = fmaxf(mxB, __shfl_xor_sync(0xffffffffu, mxB, off));
        }
        float mA = fmaxf(m0, mxA), mB = fmaxf(m1, mxB);
        float sc0 = expf(m0 - mA), sc1 = expf(m1 - mB);

        float sumA = 0.f, sumB = 0.f;
        float pr[4][4];
        #pragma unroll
        for (int nt = 0; nt < 4; nt++) {
            pr[nt][0] = expf(s[nt][0] - mA);
            pr[nt][1] = expf(s[nt][1] - mA);
            pr[nt][2] = expf(s[nt][2] - mB);
            pr[nt][3] = expf(s[nt][3] - mB);
            sumA += pr[nt][0] + pr[nt][1];
            sumB += pr[nt][2] + pr[nt][3];
        }
        #pragma unroll
        for (int off = 1; off <= 2; off <<= 1) {
            sumA += __shfl_xor_sync(0xffffffffu, sumA, off);
            sumB += __shfl_xor_sync(0xffffffffu, sumB, off);
        }
        l0 = l0 * sc0 + sumA;
        l1 = l1 * sc1 + sumB;
        m0 = mA; m1 = mB;

        // write P (tf32-rounded) to warp-private smem rows
        #pragma unroll
        for (int nt = 0; nt < 4; nt++) {
            float2 pa = make_float2(ftf32(pr[nt][0]), ftf32(pr[nt][1]));
            float2 pb = make_float2(ftf32(pr[nt][2]), ftf32(pr[nt][3]));
            *reinterpret_cast<float2*>(&Ps[rA * PP + nt * 8 + cq * 2]) = pa;
            *reinterpret_cast<float2*>(&Ps[(rA + 8) * PP + nt * 8 + cq * 2]) = pb;
        }
        __syncwarp();

        // rescale O, then O += P @ V
        #pragma unroll
        for (int nt = 0; nt < 4; nt++) {
            o[nt][0] *= sc0; o[nt][1] *= sc0;
            o[nt][2] *= sc1; o[nt][3] *= sc1;
        }
        const uint32_t* psp = reinterpret_cast<const uint32_t*>(Ps);
        const uint32_t* vsp = reinterpret_cast<const uint32_t*>(Vs);
        #pragma unroll
        for (int ks = 0; ks < 4; ks++) {
            int cb = ks * 8 + cq;
            uint32_t a0 = psp[rA * PP + cb];
            uint32_t a1 = psp[(rA + 8) * PP + cb];
            uint32_t a2 = psp[rA * PP + cb + 4];
            uint32_t a3 = psp[(rA + 8) * PP + cb + 4];
            #pragma unroll
            for (int nt = 0; nt < 4; nt++) {
                int nb = nt * 8 + (lane >> 2);
                uint32_t b0 = vsp[nb * VP + cb];
                uint32_t b1 = vsp[nb * VP + cb + 4];
                float* c = o[nt];
                asm volatile(
                    "mma.sync.aligned.m16n8k8.row.col.f32.tf32.tf32.f32 "
                    "{%0,%1,%2,%3}, {%4,%5,%6,%7}, {%8,%9}, {%0,%1,%2,%3};"
                    : "+f"(c[0]), "+f"(c[1]), "+f"(c[2]), "+f"(c[3])
                    : "r"(a0), "r"(a1), "r"(a2), "r"(a3), "r"(b0), "r"(b1));
            }
        }
        __syncthreads();
    }

    // epilogue: O / l  -> sa[(q*BSZ+b)][h*32 + d]
    float i0 = 1.f / l0, i1 = 1.f / l1;
    #pragma unroll
    for (int nt = 0; nt < 4; nt++) {
        int col = h * HD + nt * 8 + cq * 2;
        long rowA = (long)(q0 + rA) * BSZ + b;
        long rowB = (long)(q0 + rA + 8) * BSZ + b;
        *reinterpret_cast<float2*>(&sa[rowA * DIM + col]) =
            make_float2(o[nt][0] * i0, o[nt][1] * i0);
        *reinterpret_cast<float2*>(&sa[rowB * DIM + col]) =
            make_float2(o[nt][2] * i1, o[nt][3] * i1);
    }
}

// ---------------------------------------------------------------------------
// Inverse L2 norm of each memory row (m,b)
// ---------------------------------------------------------------------------
__global__ void inv_norm_kernel(const float* __restrict__ mem, float* __restrict__ mnorm)
{
    int r    = blockIdx.x * 8 + (threadIdx.x >> 5);
    int lane = threadIdx.x & 31;
    const float* p = mem + (long)r * DIM;
    float s = 0.f;
    #pragma unroll
    for (int j = lane; j < DIM; j += 32) { float x = p[j]; s = fmaf(x, x, s); }
    #pragma unroll
    for (int o = 16; o; o >>= 1) s += __shfl_xor_sync(0xffffffffu, s, o);
    if (lane == 0) mnorm[r] = 1.0f / sqrtf(s);
}

// ---------------------------------------------------------------------------
// Radix-select top-32 per (n,b) row. Exact threshold; lowest-index ties.
// ---------------------------------------------------------------------------
__global__ void topk_radix(const float* __restrict__ sim,
                           const float* __restrict__ mnorm,
                           int* __restrict__ rns)
{
    int n = blockIdx.x, b = blockIdx.y;
    const float* row = sim + ((long)b * NP + n) * MNP;
    int t = threadIdx.x;

    __shared__ uint32_t sv[MNP];
    __shared__ uint32_t hist[256];
    __shared__ uint32_t sh_prefix, sh_needed, sh_cnt, sh_ecnt;
    __shared__ int elist[64];

    #pragma unroll
    for (int j = 0; j < MNP / 256; j++) {
        int m = t + j * 256;
        float v = row[m] * mnorm[m * BSZ + b];
        uint32_t u = __float_as_uint(v);
        u = (u & 0x80000000u) ? ~u : (u | 0x80000000u);   // order-preserving map
        sv[m] = u;
    }

    uint32_t prefix = 0, pmask = 0;
    int needed = TOPK;

    for (int shift = 24; shift >= 0; shift -= 8) {
        hist[t] = 0;
        __syncthreads();
        #pragma unroll
        for (int j = 0; j < MNP / 256; j++) {
            uint32_t u = sv[t + j * 256];
            if ((u & pmask) == prefix) atomicAdd(&hist[(u >> shift) & 255u], 1u);
        }
        __syncthreads();
        if (t == 0) {
            int cum = 0, bsel = 0;
            for (int bb = 255; bb >= 0; bb--) {
                int hcnt = (int)hist[bb];
                if (cum + hcnt >= needed) { bsel = bb; break; }
                cum += hcnt;
            }
            sh_prefix = prefix | ((uint32_t)bsel << shift);
            sh_needed = (uint32_t)(needed - cum);
        }
        __syncthreads();
        prefix = sh_prefix;
        needed = (int)sh_needed;
        pmask |= (0xFFu << shift);
        __syncthreads();
    }

    if (t == 0) { sh_cnt = 0; sh_ecnt = 0; }
    __syncthreads();

    const uint32_t T = prefix;
    const int rem = needed;
    int* out = rns + ((long)b * NP + n) * TOPK;

    #pragma unroll
    for (int j = 0; j < MNP / 256; j++) {
        int m = t + j * 256;
        uint32_t u = sv[m];
        if (u > T) {
            int pos = (int)atomicAdd(&sh_cnt, 1u);
            out[pos] = m;
        } else if (u == T) {
            int ep = (int)atomicAdd(&sh_ecnt, 1u);
            if (ep < 64) elist[ep] = m;
        }
    }
    __syncthreads();

    if (t == 0) {
        int base = (int)sh_cnt;                 // == TOPK - rem
        int ec = (int)sh_ecnt; if (ec > 64) ec = 64;
        int last = -1;
        for (int i = 0; i < rem; i++) {
            int best = 0x7fffffff;
            for (int j = 0; j < ec; j++) {
                int v = elist[j];
                if (v > last && v < best) best = v;
            }
            out[base + i] = best;
            last = best;
        }
    }
}

// ---------------------------------------------------------------------------
// Fused sparse cross-attention + LN1: t1 = LN(tgt + crossattn)
// Block (n,b), 256 threads: warp h handles head h, lane = dim within head.
// ---------------------------------------------------------------------------
__global__ void cross_ln_kernel(const float* __restrict__ Q,
                                const float* __restrict__ Kb,
                                const float* __restrict__ Vb,
                                const int*   __restrict__ rns,
                                const float* __restrict__ tgt,
                                const float* __restrict__ w,
                                const float* __restrict__ beta,
                                float* __restrict__ t1)
{
    int n = blockIdx.x, b = blockIdx.y;
    int t = threadIdx.x, h = t >> 5, lane = t & 31;
    __shared__ int idx[TOPK];
    __shared__ float red[8];
    if (t < TOPK) idx[t] = rns[((long)b * NP + n) * TOPK + t];
    __syncthreads();

    long rowoff = ((long)n * BSZ + b) * DIM;
    float q = Q[rowoff + h * HD + lane];

    float myscore = -INFINITY;
    #pragma unroll
    for (int j = 0; j < TOPK; j++) {
        float prod = q * Kb[((long)idx[j] * BSZ + b) * DIM + h * HD + lane];
        #pragma unroll
        for (int o = 16; o; o >>= 1) prod += __shfl_xor_sync(0xffffffffu, prod, o);
        if (lane == j) myscore = prod * ATT_SCALE;
    }
    float mx = myscore;
    #pragma unroll
    for (int o = 16; o; o >>= 1) mx = fmaxf(mx, __shfl_xor_sync(0xffffffffu, mx, o));
    float e = expf(myscore - mx);
    float s = e;
    #pragma unroll
    for (int o = 16; o; o >>= 1) s += __shfl_xor_sync(0xffffffffu, s, o);
    float p = e / s;

    float acc = 0.f;
    #pragma unroll
    for (int j = 0; j < TOPK; j++) {
        float pj = __shfl_sync(0xffffffffu, p, j);
        acc = fmaf(pj, Vb[((long)idx[j] * BSZ + b) * DIM + h * HD + lane], acc);
    }

    // LN over the 256-dim row (thread t owns dim t = h*32+lane)
    float x = tgt[rowoff + t] + acc;
    float sum = x;
    #pragma unroll
    for (int o = 16; o; o >>= 1) sum += __shfl_xor_sync(0xffffffffu, sum, o);
    if (lane == 0) red[h] = sum;
    __syncthreads();
    float tot = 0.f;
    #pragma unroll
    for (int k = 0; k < 8; k++) tot += red[k];
    float mu = tot * (1.0f / DIM);
    __syncthreads();

    float d = x - mu;
    float s2 = d * d;
    #pragma unroll
    for (int o = 16; o; o >>= 1) s2 += __shfl_xor_sync(0xffffffffu, s2, o);
    if (lane == 0) red[h] = s2;
    __syncthreads();
    float tot2 = 0.f;
    #pragma unroll
    for (int k = 0; k < 8; k++) tot2 += red[k];
    float var = tot2 * (1.0f / DIM);

    t1[rowoff + t] = d * rsqrtf(var + LN_EPS) * w[t] + beta[t];
}

// ---------------------------------------------------------------------------
// out = LayerNorm(a + c) * w + beta
// ---------------------------------------------------------------------------
__global__ void add_ln_kernel(const float* __restrict__ a, const float* __restrict__ c,
                              const float* __restrict__ w, const float* __restrict__ beta,
                              float* __restrict__ out)
{
    long r = blockIdx.x;
    int  t = threadIdx.x;
    float x = a[r * DIM + t] + c[r * DIM + t];
    __shared__ float red[8];

    float s = x;
    #pragma unroll
    for (int o = 16; o; o >>= 1) s += __shfl_xor_sync(0xffffffffu, s, o);
    if ((t & 31) == 0) red[t >> 5] = s;
    __syncthreads();
    float tot = 0.f;
    #pragma unroll
    for (int k = 0; k < 8; k++) tot += red[k];
    float mu = tot * (1.0f / DIM);
    __syncthreads();

    float d  = x - mu;
    float s2 = d * d;
    #pragma unroll
    for (int o = 16; o; o >>= 1) s2 += __shfl_xor_sync(0xffffffffu, s2, o);
    if ((t & 31) == 0) red[t >> 5] = s2;
    __syncthreads();
    float tot2 = 0.f;
    #pragma unroll
    for (int k = 0; k < 8; k++) tot2 += red[k];
    float var = tot2 * (1.0f / DIM);

    out[r * DIM + t] = d * rsqrtf(var + LN_EPS) * w[t] + beta[t];
}

// ---------------------------------------------------------------------------
// out = LN(t2 + p0 + p1 + bias) — fused FFN2 split-K reduction + final LN
// ---------------------------------------------------------------------------
__global__ void ln3_fused_kernel(const float* __restrict__ t2,
                                 const float* __restrict__ p0,
                                 const float* __restrict__ p1,
                                 const float* __restrict__ bias,
                                 const float* __restrict__ w,
                                 const float* __restrict__ beta,
                                 float* __restrict__ out)
{
    long r = blockIdx.x;
    int  t = threadIdx.x;
    float x = t2[r * DIM + t] + (p0[r * DIM + t] + p1[r * DIM + t] + bias[t]);
    __shared__ float red[8];

    float s = x;
    #pragma unroll
    for (int o = 16; o; o >>= 1) s += __shfl_xor_sync(0xffffffffu, s, o);
    if ((t & 31) == 0) red[t >> 5] = s;
    __syncthreads();
    float tot = 0.f;
    #pragma unroll
    for (int k = 0; k < 8; k++) tot += red[k];
    float mu = tot * (1.0f / DIM);
    __syncthreads();

    float d  = x - mu;
    float s2 = d * d;
    #pragma unroll
    for (int o = 16; o; o >>= 1) s2 += __shfl_xor_sync(0xffffffffu, s2, o);
    if ((t & 31) == 0) red[t >> 5] = s2;
    __syncthreads();
    float tot2 = 0.f;
    #pragma unroll
    for (int k = 0; k < 8; k++) tot2 += red[k];
    float var = tot2 * (1.0f / DIM);

    out[r * DIM + t] = d * rsqrtf(var + LN_EPS) * w[t] + beta[t];
}

// ---------------------------------------------------------------------------
// Launch
// ---------------------------------------------------------------------------
extern "C" void kernel_launch(void* const* d_in, const int* in_sizes, int n_in,
                              void* d_out, int out_size)
{
    const float* tgt      = (const float*)d_in[0];
    const float* memory   = (const float*)d_in[1];
    const float* qpos     = (const float*)d_in[2];
    const float* kpos     = (const float*)d_in[3];
    const float* cw1      = (const float*)d_in[4];
    const float* cb1      = (const float*)d_in[5];
    const float* cw2      = (const float*)d_in[6];
    const float* cb2      = (const float*)d_in[7];
    const float* cw3      = (const float*)d_in[8];
    const float* cb3      = (const float*)d_in[9];
    const float* sa_in_w  = (const float*)d_in[10];
    const float* sa_in_b  = (const float*)d_in[11];
    const float* sa_out_w = (const float*)d_in[12];
    const float* sa_out_b = (const float*)d_in[13];
    const float* ln1_w    = (const float*)d_in[14];
    const float* ln1_b    = (const float*)d_in[15];
    const float* ln2_w    = (const float*)d_in[16];
    const float* ln2_b    = (const float*)d_in[17];
    const float* ln3_w    = (const float*)d_in[18];
    const float* ln3_b    = (const float*)d_in[19];
    const float* ff1_w    = (const float*)d_in[20];
    const float* ff1_b    = (const float*)d_in[21];
    const float* ff2_w    = (const float*)d_in[22];
    const float* ff2_b    = (const float*)d_in[23];
    float* out = (float*)d_out;

    void *p;
    cudaGetSymbolAddress(&p, g_sim);   float* sim   = (float*)p;
    cudaGetSymbolAddress(&p, g_mnorm); float* mnorm = (float*)p;
    cudaGetSymbolAddress(&p, g_rns);   int*   rns   = (int*)p;
    cudaGetSymbolAddress(&p, g_K);     float* Kb    = (float*)p;
    cudaGetSymbolAddress(&p, g_V);     float* Vb    = (float*)p;
    cudaGetSymbolAddress(&p, g_Q);     float* Qb    = (float*)p;
    cudaGetSymbolAddress(&p, g_t1);    float* t1    = (float*)p;
    cudaGetSymbolAddress(&p, g_QK2);   float* QK2   = (float*)p;
    cudaGetSymbolAddress(&p, g_V2);    float* V2    = (float*)p;
    cudaGetSymbolAddress(&p, g_sa);    float* sa    = (float*)p;
    cudaGetSymbolAddress(&p, g_sa2);   float* sa2   = (float*)p;
    cudaGetSymbolAddress(&p, g_t2);    float* t2    = (float*)p;
    cudaGetSymbolAddress(&p, g_ffh);   float* ffh   = (float*)p;
    cudaGetSymbolAddress(&p, g_ffo);   float* ffo   = (float*)p;
    cudaGetSymbolAddress(&p, g_madd);  float* madd  = (float*)p;
    cudaGetSymbolAddress(&p, g_qadd);  float* qadd  = (float*)p;

    const long BD = (long)BSZ * DIM;   // 2048

    // 1) inverse norms
    inv_norm_kernel<<<MNP * BSZ / 8, 256>>>(memory, mnorm);

    // 2) sim (exact fp32)
    sim_sgemm2<<<dim3(MNP / 128, NP / 128, BSZ), 256>>>(
        tgt, memory, sim, DIM, (int)BD, (int)BD, MNP, DIM, DIM, (long)NP * MNP);

    // 3) radix top-32
    topk_radix<<<dim3(NP, BSZ), 256>>>(sim, mnorm, rns);

    // pre-adds
    vecadd_kernel<<<(MNP * BSZ * DIM / 4 + 255) / 256, 256>>>(memory, kpos, madd, MNP * BSZ * DIM / 4);
    vecadd_kernel<<<(NP * BSZ * DIM / 4 + 255) / 256, 256>>>(tgt, qpos, qadd, NP * BSZ * DIM / 4);

    // 4) cross projections
    tgemm_nt<0><<<dim3(DIM / 64, MNP * BSZ / 128, 1), 256>>>(
        madd, cw2, cb2, Kb,
        MNP * BSZ, DIM, DIM, DIM, DIM, DIM, 0, 0, 0, 0, 0, 0, 1, 1.0f);
    tgemm_nt<0><<<dim3(DIM / 64, MNP * BSZ / 128, 1), 256>>>(
        memory, cw3, cb3, Vb,
        MNP * BSZ, DIM, DIM, DIM, DIM, DIM, 0, 0, 0, 0, 0, 0, 1, 1.0f);
    tgemm_nt<0><<<dim3(DIM / 64, NP * BSZ / 128, 1), 256>>>(
        qadd, cw1, cb1, Qb,
        NP * BSZ, DIM, DIM, DIM, DIM, DIM, 0, 0, 0, 0, 0, 0, 1, 1.0f);

    // 5) sparse cross-attention + LN1 fused
    cross_ln_kernel<<<dim3(NP, BSZ), 256>>>(Qb, Kb, Vb, rns, tgt, ln1_w, ln1_b, t1);

    // 6) self-attn projections
    vecadd_kernel<<<(NP * BSZ * DIM / 4 + 255) / 256, 256>>>(t1, qpos, qadd, NP * BSZ * DIM / 4);
    tgemm_nt<0><<<dim3(2 * DIM / 64, NP * BSZ / 128, 1), 256>>>(
        qadd, sa_in_w, sa_in_b, QK2,
        NP * BSZ, 2 * DIM, DIM, DIM, DIM, 2 * DIM, 0, 0, 0, 0, 0, 0, 1, 1.0f);
    tgemm_nt<0><<<dim3(DIM / 64, NP * BSZ / 128, 1), 256>>>(
        t1, sa_in_w + 2 * DIM * DIM, sa_in_b + 2 * DIM, V2,
        NP * BSZ, DIM, DIM, DIM, DIM, DIM, 0, 0, 0, 0, 0, 0, 1, 1.0f);

    // 7) fused flash self-attention -> sa
    flash_sa_kernel<<<dim3(NP / 128, BSZ * NH), 256>>>(QK2, V2, sa);

    // 8) out projection, t2 = LN(t1 + sa2)
    tgemm_nt<0><<<dim3(DIM / 64, NP * BSZ / 128, 1), 256>>>(
        sa, sa_out_w, sa_out_b, sa2,
        NP * BSZ, DIM, DIM, DIM, DIM, DIM, 0, 0, 0, 0, 0, 0, 1, 1.0f);
    add_ln_kernel<<<NP * BSZ, 256>>>(t1, sa2, ln2_w, ln2_b, t2);

    // 9) FFN: gelu GEMM, then split-K=2 second GEMM, then fused reduce+LN
    tgemm_nt<1><<<dim3(FF / 64, NP * BSZ / 128, 1), 256>>>(
        t2, ff1_w, ff1_b, ffh,
        NP * BSZ, FF, DIM, DIM, DIM, FF, 0, 0, 0, 0, 0, 0, 1, 1.0f);
    tgemm_nt<0><<<dim3(DIM / 64, NP * BSZ / 128, 2), 256>>>(
        ffh, ff2_w, nullptr, ffo,
        NP * BSZ, DIM, FF / 2, FF, FF, DIM,
        0, FF / 2, 0, FF / 2, 0, (long)NP * BSZ * DIM, 2, 1.0f);
    ln3_fused_kernel<<<NP * BSZ, 256>>>(t2, ffo, ffo + (long)NP * BSZ * DIM,
                                        ff2_b, ln3_w, ln3_b, out);
}